// round 13
// baseline (speedup 1.0000x reference)
#include <cuda_runtime.h>
#include <cuda_bf16.h>
#include <stdint.h>
#include <math.h>

#define DD 1024
#define LL 3072
#define NMEL 100
#define NB 4
#define NT_SEQ 1024
#define ROWS (NB*NT_SEQ)

// ---------------- fp32 scratch ----------------
__device__ float g_wproj[DD*DD];
__device__ float g_wprime[DD*DD];
__device__ float g_u[DD*DD];
__device__ float g_Qf[DD*DD];
__device__ float g_fused[ROWS*DD];
__device__ float g_h1[ROWS*DD];
__device__ float g_h2[ROWS*DD];
__device__ float g_bvec[DD];

// ---------------- bf16 split scratch ----------------
__device__ __nv_bfloat16 g_WinD_h[DD*LL];
__device__ __nv_bfloat16 g_WinD_l[DD*LL];
__device__ __nv_bfloat16 g_WdD_h[DD*LL];
__device__ __nv_bfloat16 g_WdD_l[DD*LL];
__device__ __nv_bfloat16 g_WinT_h[LL*DD];
__device__ __nv_bfloat16 g_WinT_l[LL*DD];
__device__ __nv_bfloat16 g_Lla_h[ROWS*LL];
__device__ __nv_bfloat16 g_Lla_l[ROWS*LL];
__device__ __nv_bfloat16 g_Pd_h[DD*DD];
__device__ __nv_bfloat16 g_Pd_l[DD*DD];
__device__ __nv_bfloat16 g_Pt_h[DD*DD];
__device__ __nv_bfloat16 g_Pt_l[DD*DD];
__device__ __nv_bfloat16 g_wpT_h[DD*DD];
__device__ __nv_bfloat16 g_wpT_l[DD*DD];
__device__ __nv_bfloat16 g_t1s_h[DD*DD];
__device__ __nv_bfloat16 g_t1s_l[DD*DD];
__device__ __nv_bfloat16 g_S_h[DD*DD];
__device__ __nv_bfloat16 g_S_l[DD*DD];
__device__ __nv_bfloat16 g_uT_h[DD*DD];
__device__ __nv_bfloat16 g_uT_l[DD*DD];
__device__ __nv_bfloat16 g_QT_h[DD*DD];
__device__ __nv_bfloat16 g_QT_l[DD*DD];
__device__ __nv_bfloat16 g_WcTs_h[DD*LL];
__device__ __nv_bfloat16 g_WcTs_l[DD*LL];
__device__ __nv_bfloat16 g_xn_h[ROWS*DD];
__device__ __nv_bfloat16 g_xn_l[ROWS*DD];
__device__ __nv_bfloat16 g_Wmel_h[128*DD];
__device__ __nv_bfloat16 g_Wmel_l[128*DD];

// ---------------- device helpers ----------------
__device__ __forceinline__ void split2(float x, __nv_bfloat16& h, __nv_bfloat16& l) {
    h = __float2bfloat16_rn(x);
    l = __float2bfloat16_rn(x - __bfloat162float(h));
}

__device__ __forceinline__ unsigned smaddr(const void* p) {
    return (unsigned)__cvta_generic_to_shared(p);
}

__device__ __forceinline__ void ldm_x4(uint32_t* r, unsigned a) {
    asm volatile("ldmatrix.sync.aligned.m8n8.x4.shared.b16 {%0,%1,%2,%3}, [%4];"
        : "=r"(r[0]), "=r"(r[1]), "=r"(r[2]), "=r"(r[3]) : "r"(a));
}

__device__ __forceinline__ void mma16816(float* d, const uint32_t* a, const uint32_t* b) {
    asm volatile("mma.sync.aligned.m16n8k16.row.col.f32.bf16.bf16.f32 "
        "{%0,%1,%2,%3}, {%4,%5,%6,%7}, {%8,%9}, {%0,%1,%2,%3};"
        : "+f"(d[0]), "+f"(d[1]), "+f"(d[2]), "+f"(d[3])
        : "r"(a[0]), "r"(a[1]), "r"(a[2]), "r"(a[3]), "r"(b[0]), "r"(b[1]));
}

__device__ __forceinline__ void cpa16(unsigned sm, const void* g) {
    asm volatile("cp.async.cg.shared.global [%0], [%1], 16;" :: "r"(sm), "l"(g));
}

__device__ __forceinline__ void cpa_commit() {
    asm volatile("cp.async.commit_group;");
}

template<int W>
__device__ __forceinline__ void cpa_wait() {
    asm volatile("cp.async.wait_group %0;" :: "n"(W));
}

// ---------------- convert bodies ----------------
__device__ void split_dir_body(const float* in, __nv_bfloat16* hi, __nv_bfloat16* lo, int n4)
{
    int i = blockIdx.x * blockDim.x + threadIdx.x;
    if (i >= n4) return;
    float4 v = ((const float4*)in)[i];
    __nv_bfloat16 h0, h1, h2, h3, l0, l1, l2, l3;
    split2(v.x, h0, l0);
    split2(v.y, h1, l1);
    split2(v.z, h2, l2);
    split2(v.w, h3, l3);
    ((__nv_bfloat162*)hi)[2*i+0] = __nv_bfloat162(h0, h1);
    ((__nv_bfloat162*)hi)[2*i+1] = __nv_bfloat162(h2, h3);
    ((__nv_bfloat162*)lo)[2*i+0] = __nv_bfloat162(l0, l1);
    ((__nv_bfloat162*)lo)[2*i+1] = __nv_bfloat162(l2, l3);
}

template<bool SIG>
__device__ void split_trans_body(const float* in, const float* mask,
                                 __nv_bfloat16* hi, __nv_bfloat16* lo, int P_, int Q_)
{
    __shared__ float t[32][33];
    int p0 = blockIdx.x * 32;
    int q0 = blockIdx.y * 32;
    int tx = threadIdx.x;
    int ty = threadIdx.y;
    #pragma unroll
    for (int dy = 0; dy < 32; dy += 8) {
        size_t idx = (size_t)(p0 + ty + dy) * Q_ + q0 + tx;
        float v = in[idx];
        if (SIG) v *= 1.f / (1.f + __expf(-mask[idx]));
        t[ty + dy][tx] = v;
    }
    __syncthreads();
    #pragma unroll
    for (int dy = 0; dy < 32; dy += 8) {
        float v = t[tx][ty + dy];
        __nv_bfloat16 h, l;
        split2(v, h, l);
        size_t o = (size_t)(q0 + ty + dy) * P_ + p0 + tx;
        hi[o] = h;
        lo[o] = l;
    }
}

// ---------------- pipelined split-bf16 mma.sync GEMM ----------------
// C[M,N] = A[M,K] @ Bt[N,K]^T (+bias); 3-stage cp.async ring, one sync/iter.
// Pass-major MMA ordering (hh*8, hl*8, lh*8) to break accumulator RAW chains.
// EPI 0: fp32 C.  EPI 1: bf16 hi/lo split outputs Oh/Ol (no bias).  EPI 2: mel transposed.
template<int MI, int NJ, int EPI>
__device__ void gemm_body(const __nv_bfloat16* Ahi, const __nv_bfloat16* Alo,
                          const __nv_bfloat16* Bhi, const __nv_bfloat16* Blo,
                          const float* bias, float* C,
                          __nv_bfloat16* Oh, __nv_bfloat16* Ol,
                          int M, int N, int K)
{
    constexpr int BM = 2 * MI * 16;
    constexpr int BN = 4 * NJ * 8;
    constexpr int STRIDE = (2 * BM + 2 * BN) * 40;   // elems per stage
    extern __shared__ __nv_bfloat16 dyn[];

    const int tid = threadIdx.x;
    const int warp = tid >> 5;
    const int lane = tid & 31;
    const int wm = warp & 1;
    const int wn = warp >> 1;
    const int m0b = blockIdx.y * BM;
    const int n0b = blockIdx.x * BN;
    const int wm0 = wm * MI * 16;
    const int wn0 = wn * NJ * 8;

    float acc[MI][NJ][4];
    #pragma unroll
    for (int i = 0; i < MI; ++i)
        #pragma unroll
        for (int j = 0; j < NJ; ++j)
            #pragma unroll
            for (int c = 0; c < 4; ++c) acc[i][j][c] = 0.f;

    const int lr0 = tid >> 2;
    const int lc  = (tid & 3) * 8;
    const int a_row = lane & 15;
    const int a_col = (lane >> 4) * 8;
    const int b_row = (lane & 7) + ((lane >> 4) << 3);
    const int b_col = ((lane >> 3) & 1) * 8;

    const int nk = K >> 5;

    auto load_stage = [&](int st, int k0) {
        __nv_bfloat16* sAh = dyn + st * STRIDE;
        __nv_bfloat16* sAl = sAh + BM * 40;
        __nv_bfloat16* sBh = sAl + BM * 40;
        __nv_bfloat16* sBl = sBh + BN * 40;
        #pragma unroll
        for (int h = 0; h < BM / 64; ++h) {
            int r = lr0 + h * 64;
            size_t ga = (size_t)(m0b + r) * K + k0 + lc;
            cpa16(smaddr(sAh + r * 40 + lc), Ahi + ga);
            cpa16(smaddr(sAl + r * 40 + lc), Alo + ga);
        }
        #pragma unroll
        for (int h = 0; h < BN / 64; ++h) {
            int r = lr0 + h * 64;
            size_t gb = (size_t)(n0b + r) * K + k0 + lc;
            cpa16(smaddr(sBh + r * 40 + lc), Bhi + gb);
            cpa16(smaddr(sBl + r * 40 + lc), Blo + gb);
        }
        cpa_commit();
    };

    auto compute_stage = [&](int st) {
        __nv_bfloat16* sAh = dyn + st * STRIDE;
        __nv_bfloat16* sAl = sAh + BM * 40;
        __nv_bfloat16* sBh = sAl + BM * 40;
        __nv_bfloat16* sBl = sBh + BN * 40;
        #pragma unroll
        for (int ks = 0; ks < 32; ks += 16) {
            uint32_t ah[MI][4];
            uint32_t al[MI][4];
            uint32_t bh[NJ][2];
            uint32_t bl[NJ][2];
            #pragma unroll
            for (int mi = 0; mi < MI; ++mi) {
                ldm_x4(ah[mi], smaddr(sAh + (wm0 + mi*16 + a_row) * 40 + ks + a_col));
                ldm_x4(al[mi], smaddr(sAl + (wm0 + mi*16 + a_row) * 40 + ks + a_col));
            }
            #pragma unroll
            for (int njp = 0; njp < NJ / 2; ++njp) {
                uint32_t t[4];
                ldm_x4(t, smaddr(sBh + (wn0 + njp*16 + b_row) * 40 + ks + b_col));
                bh[njp*2][0] = t[0];
                bh[njp*2][1] = t[1];
                bh[njp*2+1][0] = t[2];
                bh[njp*2+1][1] = t[3];
                ldm_x4(t, smaddr(sBl + (wn0 + njp*16 + b_row) * 40 + ks + b_col));
                bl[njp*2][0] = t[0];
                bl[njp*2][1] = t[1];
                bl[njp*2+1][0] = t[2];
                bl[njp*2+1][1] = t[3];
            }
            // pass-major: all hh, then all hl, then all lh -> 7 independent MMAs
            // between successive writes to any accumulator.
            #pragma unroll
            for (int mi = 0; mi < MI; ++mi)
                #pragma unroll
                for (int nj = 0; nj < NJ; ++nj)
                    mma16816(acc[mi][nj], ah[mi], bh[nj]);
            #pragma unroll
            for (int mi = 0; mi < MI; ++mi)
                #pragma unroll
                for (int nj = 0; nj < NJ; ++nj)
                    mma16816(acc[mi][nj], ah[mi], bl[nj]);
            #pragma unroll
            for (int mi = 0; mi < MI; ++mi)
                #pragma unroll
                for (int nj = 0; nj < NJ; ++nj)
                    mma16816(acc[mi][nj], al[mi], bh[nj]);
        }
    };

    load_stage(0, 0);
    if (nk > 1) load_stage(1, 32);
    for (int c = 0; c < nk; ++c) {
        if (c + 1 < nk) cpa_wait<1>();
        else            cpa_wait<0>();
        __syncthreads();
        if (c + 2 < nk) load_stage((c + 2) % 3, (c + 2) * 32);
        compute_stage(c % 3);
    }

    const int g = lane >> 2;
    const int tg = lane & 3;
    #pragma unroll
    for (int mi = 0; mi < MI; ++mi)
        #pragma unroll
        for (int nj = 0; nj < NJ; ++nj) {
            int m = m0b + wm0 + mi * 16 + g;
            int n = n0b + wn0 + nj * 8 + tg * 2;
            float v0 = acc[mi][nj][0];
            float v1 = acc[mi][nj][1];
            float v2 = acc[mi][nj][2];
            float v3 = acc[mi][nj][3];
            if (EPI == 0) {
                if (bias) {
                    v0 += bias[n];
                    v1 += bias[n+1];
                    v2 += bias[n];
                    v3 += bias[n+1];
                }
                C[(size_t)m * N + n]       = v0;
                C[(size_t)m * N + n + 1]   = v1;
                C[(size_t)(m+8) * N + n]   = v2;
                C[(size_t)(m+8) * N + n+1] = v3;
            } else if (EPI == 1) {
                __nv_bfloat16 h0, h1, h2, h3, l0, l1, l2, l3;
                split2(v0, h0, l0);
                split2(v1, h1, l1);
                split2(v2, h2, l2);
                split2(v3, h3, l3);
                *(__nv_bfloat162*)(Oh + (size_t)m * N + n)       = __nv_bfloat162(h0, h1);
                *(__nv_bfloat162*)(Ol + (size_t)m * N + n)       = __nv_bfloat162(l0, l1);
                *(__nv_bfloat162*)(Oh + (size_t)(m+8) * N + n)   = __nv_bfloat162(h2, h3);
                *(__nv_bfloat162*)(Ol + (size_t)(m+8) * N + n)   = __nv_bfloat162(l2, l3);
            } else {
                float bn0 = (n < NMEL) ? bias[n] : 0.f;
                float bn1 = (n + 1 < NMEL) ? bias[n + 1] : 0.f;
                v0 += bn0;
                v1 += bn1;
                v2 += bn0;
                v3 += bn1;
                int bb = m >> 10;
                int t = m & 1023;
                int bb2 = (m + 8) >> 10;
                int t2 = (m + 8) & 1023;
                if (n < NMEL) {
                    C[(size_t)(bb*NMEL + n) * NT_SEQ + t] = v0;
                    C[(size_t)(bb2*NMEL + n) * NT_SEQ + t2] = v2;
                }
                if (n + 1 < NMEL) {
                    C[(size_t)(bb*NMEL + n+1) * NT_SEQ + t] = v1;
                    C[(size_t)(bb2*NMEL + n+1) * NT_SEQ + t2] = v3;
                }
            }
        }
}

// ---------------- conv / ln bodies ----------------
template<bool DO_GELU>
__device__ void conv_body(const float* in, const float* w, const float* bias, float* out)
{
    __shared__ float sm[10][DD];
    const int blk = blockIdx.x;
    const int b  = blk / (NT_SEQ / 8);
    const int t0 = (blk % (NT_SEQ / 8)) * 8;
    const float* inb = in + (size_t)b * NT_SEQ * DD;
    const int tid = threadIdx.x;

    for (int idx = tid; idx < 10 * DD; idx += 256) {
        int r = idx / DD;
        int c = idx % DD;
        int t = t0 - 1 + r;
        sm[r][c] = (t >= 0 && t < NT_SEQ) ? inb[(size_t)t*DD + c] : 0.f;
    }
    __syncthreads();

    const int cbase = tid * 4;
    const int g = cbase >> 6;
    float acc[4][8];
    #pragma unroll
    for (int cc = 0; cc < 4; ++cc) {
        float bb = bias[cbase + cc];
        #pragma unroll
        for (int tt = 0; tt < 8; ++tt) acc[cc][tt] = bb;
    }
    const float* wp = w + (size_t)cbase * 192;

    for (int ci = 0; ci < 64; ++ci) {
        float x[10];
        #pragma unroll
        for (int r = 0; r < 10; ++r) x[r] = sm[r][g*64 + ci];
        #pragma unroll
        for (int cc = 0; cc < 4; ++cc) {
            float w0 = wp[cc*192 + ci*3 + 0];
            float w1 = wp[cc*192 + ci*3 + 1];
            float w2 = wp[cc*192 + ci*3 + 2];
            #pragma unroll
            for (int tt = 0; tt < 8; ++tt)
                acc[cc][tt] += w0*x[tt] + w1*x[tt+1] + w2*x[tt+2];
        }
    }

    float* outb = out + (size_t)b * NT_SEQ * DD;
    #pragma unroll
    for (int tt = 0; tt < 8; ++tt) {
        float v0 = acc[0][tt];
        float v1 = acc[1][tt];
        float v2 = acc[2][tt];
        float v3 = acc[3][tt];
        if (DO_GELU) {
            v0 = 0.5f*v0*(1.f + erff(v0*0.70710678118654752f));
            v1 = 0.5f*v1*(1.f + erff(v1*0.70710678118654752f));
            v2 = 0.5f*v2*(1.f + erff(v2*0.70710678118654752f));
            v3 = 0.5f*v3*(1.f + erff(v3*0.70710678118654752f));
        }
        float4 o;
        o.x = v0;
        o.y = v1;
        o.z = v2;
        o.w = v3;
        *(float4*)(outb + (size_t)(t0+tt)*DD + cbase) = o;
    }
}

__device__ void ln_body(const float* in, const float* gam, const float* bet,
                        __nv_bfloat16* oh, __nv_bfloat16* ol)
{
    __shared__ float s1[8];
    __shared__ float s2[8];
    const int row = blockIdx.x;
    const int tid = threadIdx.x;
    const float4* x4 = (const float4*)(in + (size_t)row * DD);
    float4 v = x4[tid];
    float s = v.x + v.y + v.z + v.w;
    float q = v.x*v.x + v.y*v.y + v.z*v.z + v.w*v.w;
    #pragma unroll
    for (int o = 16; o > 0; o >>= 1) {
        s += __shfl_xor_sync(0xFFFFFFFFu, s, o);
        q += __shfl_xor_sync(0xFFFFFFFFu, q, o);
    }
    if ((tid & 31) == 0) {
        s1[tid >> 5] = s;
        s2[tid >> 5] = q;
    }
    __syncthreads();
    float ts = 0.f;
    float tq = 0.f;
    #pragma unroll
    for (int i = 0; i < 8; ++i) {
        ts += s1[i];
        tq += s2[i];
    }
    const float mu   = ts * (1.f / DD);
    const float var  = tq * (1.f / DD) - mu * mu;
    const float rstd = rsqrtf(var + 1e-5f);
    float4 g4 = ((const float4*)gam)[tid];
    float4 b4 = ((const float4*)bet)[tid];
    float y0 = (v.x - mu) * rstd * g4.x + b4.x;
    float y1 = (v.y - mu) * rstd * g4.y + b4.y;
    float y2 = (v.z - mu) * rstd * g4.z + b4.z;
    float y3 = (v.w - mu) * rstd * g4.w + b4.w;
    __nv_bfloat16 h0, h1, h2, h3, l0, l1, l2, l3;
    split2(y0, h0, l0);
    split2(y1, h1, l1);
    split2(y2, h2, l2);
    split2(y3, h3, l3);
    size_t o = (size_t)row * DD + tid * 4;
    ((__nv_bfloat162*)(oh + o))[0] = __nv_bfloat162(h0, h1);
    ((__nv_bfloat162*)(oh + o))[1] = __nv_bfloat162(h2, h3);
    ((__nv_bfloat162*)(ol + o))[0] = __nv_bfloat162(l0, l1);
    ((__nv_bfloat162*)(ol + o))[1] = __nv_bfloat162(l2, l3);
}

// ---------------- wrapper kernels ----------------
__global__ void k_split_Win(const float* W_in) { split_dir_body(W_in, g_WinD_h, g_WinD_l, DD*LL/4); }
__global__ void k_split_Wd(const float* Wd)    { split_dir_body(Wd, g_WdD_h, g_WdD_l, DD*LL/4); }
__global__ void k_split_llama(const float* x)  { split_dir_body(x, g_Lla_h, g_Lla_l, ROWS*LL/4); }
__global__ void k_split_Pdir(const float* P)   { split_dir_body(P, g_Pd_h, g_Pd_l, DD*DD/4); }

__global__ void k_trans_WinT(const float* W_in) { split_trans_body<false>(W_in, 0, g_WinT_h, g_WinT_l, DD, LL); }
__global__ void k_trans_PT(const float* P)      { split_trans_body<false>(P, 0, g_Pt_h, g_Pt_l, DD, DD); }
__global__ void k_trans_wpT()                   { split_trans_body<false>(g_wproj, 0, g_wpT_h, g_wpT_l, DD, DD); }
__global__ void k_trans_S(const float* mask)    { split_trans_body<true>(g_wprime, mask, g_S_h, g_S_l, DD, DD); }
__global__ void k_trans_uT()                    { split_trans_body<false>(g_u, 0, g_uT_h, g_uT_l, DD, DD); }
__global__ void k_trans_QT()                    { split_trans_body<false>(g_Qf, 0, g_QT_h, g_QT_l, DD, DD); }

__global__ void k_split_mel(const float* Wmel)
{
    int i = blockIdx.x * 256 + threadIdx.x;
    int r = i >> 10;
    float v = (r < NMEL) ? Wmel[(size_t)r * DD + (i & 1023)] : 0.f;
    __nv_bfloat16 h, l;
    split2(v, h, l);
    g_Wmel_h[i] = h;
    g_Wmel_l[i] = l;
}

__global__ __launch_bounds__(256) void k_gemm_wproj(const float* bd)
{ gemm_body<2,4,0>(g_WinD_h, g_WinD_l, g_WdD_h, g_WdD_l, bd, g_wproj, 0, 0, DD, DD, LL); }

__global__ __launch_bounds__(256) void k_gemm_t1()
{ gemm_body<2,4,1>(g_Pt_h, g_Pt_l, g_wpT_h, g_wpT_l, 0, 0, g_t1s_h, g_t1s_l, DD, DD, DD); }

__global__ __launch_bounds__(256) void k_gemm_wprime()
{ gemm_body<2,4,0>(g_t1s_h, g_t1s_l, g_Pt_h, g_Pt_l, 0, g_wprime, 0, 0, DD, DD, DD); }

__global__ __launch_bounds__(256) void k_gemm_u()
{ gemm_body<2,4,0>(g_S_h, g_S_l, g_Pd_h, g_Pd_l, 0, g_u, 0, 0, DD, DD, DD); }

__global__ __launch_bounds__(256) void k_gemm_Q()
{ gemm_body<2,4,0>(g_Pd_h, g_Pd_l, g_uT_h, g_uT_l, 0, g_Qf, 0, 0, DD, DD, DD); }

__global__ __launch_bounds__(256) void k_gemm_WcT()
{ gemm_body<2,4,1>(g_QT_h, g_QT_l, g_WinT_h, g_WinT_l, 0, 0, g_WcTs_h, g_WcTs_l, DD, LL, DD); }

__global__ __launch_bounds__(256) void k_gemm_fused()
{ gemm_body<2,4,0>(g_Lla_h, g_Lla_l, g_WcTs_h, g_WcTs_l, g_bvec, g_fused, 0, 0, ROWS, DD, LL); }

__global__ __launch_bounds__(256) void k_gemm_mel(const float* bmel, float* out)
{ gemm_body<2,2,2>(g_xn_h, g_xn_l, g_Wmel_h, g_Wmel_l, bmel, out, 0, 0, ROWS, 128, DD); }

__global__ void k_bvec(const float* b_in)
{
    int e = blockIdx.x * blockDim.x + threadIdx.x;
    if (e >= DD) return;
    float s = 0.f;
    for (int d = 0; d < DD; ++d) s += b_in[d] * g_Qf[(size_t)d * DD + e];
    g_bvec[e] = s;
}

__global__ __launch_bounds__(256) void k_conv1(const float* w, const float* b)
{ conv_body<true>(g_fused, w, b, g_h1); }

__global__ __launch_bounds__(256) void k_conv2(const float* w, const float* b)
{ conv_body<false>(g_h1, w, b, g_h2); }

__global__ __launch_bounds__(256) void k_ln(const float* g, const float* b)
{ ln_body(g_h2, g, b, g_xn_h, g_xn_l); }

// ---------------- launch ----------------
extern "C" void kernel_launch(void* const* d_in, const int* in_sizes, int n_in,
                              void* d_out, int out_size)
{
    (void)in_sizes;
    (void)n_in;
    (void)out_size;
    const float* llama = (const float*)d_in[0];
    const float* W_in  = (const float*)d_in[2];
    const float* b_in  = (const float*)d_in[3];
    const float* P     = (const float*)d_in[4];
    const float* smask = (const float*)d_in[5];
    const float* Wd    = (const float*)d_in[6];
    const float* bd    = (const float*)d_in[7];
    const float* c1w   = (const float*)d_in[8];
    const float* c1b   = (const float*)d_in[9];
    const float* c2w   = (const float*)d_in[10];
    const float* c2b   = (const float*)d_in[11];
    const float* lng   = (const float*)d_in[12];
    const float* lnb   = (const float*)d_in[13];
    const float* Wmel  = (const float*)d_in[14];
    const float* bmel  = (const float*)d_in[15];
    float* out = (float*)d_out;

    // 3 stages * (2*BM + 2*BN) * 40 elems * 2B
    const int smem_64_128 = 3 * (128 + 256) * 40 * 2;   // 92160 -> 2 CTAs/SM
    const int smem_64_64  = 3 * (128 + 128) * 40 * 2;   // 61440 -> 3 CTAs/SM

    cudaFuncSetAttribute(k_gemm_wproj,  cudaFuncAttributeMaxDynamicSharedMemorySize, smem_64_128);
    cudaFuncSetAttribute(k_gemm_t1,     cudaFuncAttributeMaxDynamicSharedMemorySize, smem_64_128);
    cudaFuncSetAttribute(k_gemm_wprime, cudaFuncAttributeMaxDynamicSharedMemorySize, smem_64_128);
    cudaFuncSetAttribute(k_gemm_u,      cudaFuncAttributeMaxDynamicSharedMemorySize, smem_64_128);
    cudaFuncSetAttribute(k_gemm_Q,      cudaFuncAttributeMaxDynamicSharedMemorySize, smem_64_128);
    cudaFuncSetAttribute(k_gemm_WcT,    cudaFuncAttributeMaxDynamicSharedMemorySize, smem_64_128);
    cudaFuncSetAttribute(k_gemm_fused,  cudaFuncAttributeMaxDynamicSharedMemorySize, smem_64_128);
    cudaFuncSetAttribute(k_gemm_mel,    cudaFuncAttributeMaxDynamicSharedMemorySize, smem_64_64);

    dim3 tb(32, 8);

    // FROZEN launch order (round-12; known-good with the bench container).
    k_split_Win<<<DD*LL/4/256, 256>>>(W_in);
    k_split_Wd<<<DD*LL/4/256, 256>>>(Wd);
    k_trans_WinT<<<dim3(DD/32, LL/32), tb>>>(W_in);
    k_split_llama<<<ROWS*LL/4/256, 256>>>(llama);
    k_split_Pdir<<<DD*DD/4/256, 256>>>(P);
    k_trans_PT<<<dim3(DD/32, DD/32), tb>>>(P);
    k_split_mel<<<128*DD/256, 256>>>(Wmel);

    k_gemm_wproj<<<dim3(DD/128, DD/64), 256, smem_64_128>>>(bd);
    k_trans_wpT<<<dim3(DD/32, DD/32), tb>>>();
    k_gemm_t1<<<dim3(DD/128, DD/64), 256, smem_64_128>>>();
    k_gemm_wprime<<<dim3(DD/128, DD/64), 256, smem_64_128>>>();
    k_trans_S<<<dim3(DD/32, DD/32), tb>>>(smask);
    k_gemm_u<<<dim3(DD/128, DD/64), 256, smem_64_128>>>();
    k_trans_uT<<<dim3(DD/32, DD/32), tb>>>();
    k_gemm_Q<<<dim3(DD/128, DD/64), 256, smem_64_128>>>();
    k_trans_QT<<<dim3(DD/32, DD/32), tb>>>();
    k_bvec<<<DD/256, 256>>>(b_in);
    k_gemm_WcT<<<dim3(LL/128, DD/64), 256, smem_64_128>>>();
    k_gemm_fused<<<dim3(DD/128, ROWS/64), 256, smem_64_128>>>();

    k_conv1<<<NB * (NT_SEQ/8), 256>>>(c1w, c1b);
    k_conv2<<<NB * (NT_SEQ/8), 256>>>(c2w, c2b);
    k_ln<<<ROWS, 256>>>(lng, lnb);
    k_gemm_mel<<<dim3(2, ROWS/64), 256, smem_64_64>>>(bmel, out);
}

// round 14
// speedup vs baseline: 1.0002x; 1.0002x over previous
#include <cuda_runtime.h>
#include <cuda_bf16.h>
#include <stdint.h>
#include <math.h>

#define DD 1024
#define LL 3072
#define NMEL 100
#define NB 4
#define NT_SEQ 1024
#define ROWS (NB*NT_SEQ)

// ---------------- fp32 scratch ----------------
__device__ float g_wproj[DD*DD];
__device__ float g_wprime[DD*DD];
__device__ float g_u[DD*DD];
__device__ float g_Qf[DD*DD];
__device__ float g_fused[ROWS*DD];
__device__ float g_h1[ROWS*DD];
__device__ float g_h2[ROWS*DD];
__device__ float g_bvec[DD];

// ---------------- bf16 split scratch ----------------
__device__ __nv_bfloat16 g_WinD_h[DD*LL];
__device__ __nv_bfloat16 g_WinD_l[DD*LL];
__device__ __nv_bfloat16 g_WdD_h[DD*LL];
__device__ __nv_bfloat16 g_WdD_l[DD*LL];
__device__ __nv_bfloat16 g_WinT_h[LL*DD];
__device__ __nv_bfloat16 g_WinT_l[LL*DD];
__device__ __nv_bfloat16 g_Lla_h[ROWS*LL];
__device__ __nv_bfloat16 g_Lla_l[ROWS*LL];
__device__ __nv_bfloat16 g_Pd_h[DD*DD];
__device__ __nv_bfloat16 g_Pd_l[DD*DD];
__device__ __nv_bfloat16 g_Pt_h[DD*DD];
__device__ __nv_bfloat16 g_Pt_l[DD*DD];
__device__ __nv_bfloat16 g_wpT_h[DD*DD];
__device__ __nv_bfloat16 g_wpT_l[DD*DD];
__device__ __nv_bfloat16 g_t1s_h[DD*DD];
__device__ __nv_bfloat16 g_t1s_l[DD*DD];
__device__ __nv_bfloat16 g_S_h[DD*DD];
__device__ __nv_bfloat16 g_S_l[DD*DD];
__device__ __nv_bfloat16 g_uT_h[DD*DD];
__device__ __nv_bfloat16 g_uT_l[DD*DD];
__device__ __nv_bfloat16 g_QT_h[DD*DD];
__device__ __nv_bfloat16 g_QT_l[DD*DD];
__device__ __nv_bfloat16 g_WcTs_h[DD*LL];
__device__ __nv_bfloat16 g_WcTs_l[DD*LL];
__device__ __nv_bfloat16 g_xn_h[ROWS*DD];
__device__ __nv_bfloat16 g_xn_l[ROWS*DD];
__device__ __nv_bfloat16 g_Wmel_h[128*DD];
__device__ __nv_bfloat16 g_Wmel_l[128*DD];

// ---------------- device helpers ----------------
__device__ __forceinline__ void split2(float x, __nv_bfloat16& h, __nv_bfloat16& l) {
    h = __float2bfloat16_rn(x);
    l = __float2bfloat16_rn(x - __bfloat162float(h));
}

__device__ __forceinline__ unsigned smaddr(const void* p) {
    return (unsigned)__cvta_generic_to_shared(p);
}

__device__ __forceinline__ void ldm_x4(uint32_t* r, unsigned a) {
    asm volatile("ldmatrix.sync.aligned.m8n8.x4.shared.b16 {%0,%1,%2,%3}, [%4];"
        : "=r"(r[0]), "=r"(r[1]), "=r"(r[2]), "=r"(r[3]) : "r"(a));
}

__device__ __forceinline__ void mma16816(float* d, const uint32_t* a, const uint32_t* b) {
    asm volatile("mma.sync.aligned.m16n8k16.row.col.f32.bf16.bf16.f32 "
        "{%0,%1,%2,%3}, {%4,%5,%6,%7}, {%8,%9}, {%0,%1,%2,%3};"
        : "+f"(d[0]), "+f"(d[1]), "+f"(d[2]), "+f"(d[3])
        : "r"(a[0]), "r"(a[1]), "r"(a[2]), "r"(a[3]), "r"(b[0]), "r"(b[1]));
}

__device__ __forceinline__ void cpa16(unsigned sm, const void* g) {
    asm volatile("cp.async.cg.shared.global [%0], [%1], 16;" :: "r"(sm), "l"(g));
}

__device__ __forceinline__ void cpa_commit() {
    asm volatile("cp.async.commit_group;");
}

template<int W>
__device__ __forceinline__ void cpa_wait() {
    asm volatile("cp.async.wait_group %0;" :: "n"(W));
}

// ---------------- convert bodies ----------------
__device__ void split_dir_body(const float* in, __nv_bfloat16* hi, __nv_bfloat16* lo, int n4)
{
    int i = blockIdx.x * blockDim.x + threadIdx.x;
    if (i >= n4) return;
    float4 v = ((const float4*)in)[i];
    __nv_bfloat16 h0, h1, h2, h3, l0, l1, l2, l3;
    split2(v.x, h0, l0);
    split2(v.y, h1, l1);
    split2(v.z, h2, l2);
    split2(v.w, h3, l3);
    ((__nv_bfloat162*)hi)[2*i+0] = __nv_bfloat162(h0, h1);
    ((__nv_bfloat162*)hi)[2*i+1] = __nv_bfloat162(h2, h3);
    ((__nv_bfloat162*)lo)[2*i+0] = __nv_bfloat162(l0, l1);
    ((__nv_bfloat162*)lo)[2*i+1] = __nv_bfloat162(l2, l3);
}

template<bool SIG>
__device__ void split_trans_body(const float* in, const float* mask,
                                 __nv_bfloat16* hi, __nv_bfloat16* lo, int P_, int Q_)
{
    __shared__ float t[32][33];
    int p0 = blockIdx.x * 32;
    int q0 = blockIdx.y * 32;
    int tx = threadIdx.x;
    int ty = threadIdx.y;
    #pragma unroll
    for (int dy = 0; dy < 32; dy += 8) {
        size_t idx = (size_t)(p0 + ty + dy) * Q_ + q0 + tx;
        float v = in[idx];
        if (SIG) v *= 1.f / (1.f + __expf(-mask[idx]));
        t[ty + dy][tx] = v;
    }
    __syncthreads();
    #pragma unroll
    for (int dy = 0; dy < 32; dy += 8) {
        float v = t[tx][ty + dy];
        __nv_bfloat16 h, l;
        split2(v, h, l);
        size_t o = (size_t)(q0 + ty + dy) * P_ + p0 + tx;
        hi[o] = h;
        lo[o] = l;
    }
}

// ---------------- templated-stage split-bf16 mma.sync GEMM ----------------
// 4-stage cp.async ring; stage index is a COMPILE-TIME template parameter so all
// shared-memory addresses are loop-invariant registers and fragment arrays are
// provably register-resident.

template<int BM, int BN, int K, int ST>
__device__ __forceinline__ void g_load(unsigned ub,
    const __nv_bfloat16* Ahi, const __nv_bfloat16* Alo,
    const __nv_bfloat16* Bhi, const __nv_bfloat16* Blo,
    int m0b, int n0b, int k0, int lr0, int lc)
{
    constexpr int STRIDE = (2*BM + 2*BN) * 40;
    constexpr unsigned SOFF = (unsigned)(ST * STRIDE * 2);
    #pragma unroll
    for (int h = 0; h < BM / 64; ++h) {
        int r = lr0 + h * 64;
        size_t ga = (size_t)(m0b + r) * K + k0 + lc;
        cpa16(ub + SOFF + (unsigned)((r * 40 + lc) * 2), Ahi + ga);
        cpa16(ub + SOFF + (unsigned)((BM*40 + r * 40 + lc) * 2), Alo + ga);
    }
    #pragma unroll
    for (int h = 0; h < BN / 64; ++h) {
        int r = lr0 + h * 64;
        size_t gb = (size_t)(n0b + r) * K + k0 + lc;
        cpa16(ub + SOFF + (unsigned)((2*BM*40 + r * 40 + lc) * 2), Bhi + gb);
        cpa16(ub + SOFF + (unsigned)((2*BM*40 + BN*40 + r * 40 + lc) * 2), Blo + gb);
    }
    cpa_commit();
}

template<int MI, int NJ, int ST>
__device__ __forceinline__ void g_comp(unsigned ub, float (&acc)[MI][NJ][4],
    int wm0, int wn0, int a_row, int a_col, int b_row, int b_col)
{
    constexpr int BM = 2 * MI * 16;
    constexpr int BN = 4 * NJ * 8;
    constexpr int STRIDE = (2*BM + 2*BN) * 40;
    constexpr unsigned SOFF = (unsigned)(ST * STRIDE * 2);
    constexpr unsigned AL_OFF = (unsigned)(BM * 40 * 2);
    constexpr unsigned BH_OFF = (unsigned)(2 * BM * 40 * 2);
    constexpr unsigned BL_OFF = (unsigned)((2 * BM + BN) * 40 * 2);

    #pragma unroll
    for (int ks = 0; ks < 32; ks += 16) {
        uint32_t ah[MI][4];
        uint32_t al[MI][4];
        uint32_t bh[NJ][2];
        uint32_t bl[NJ][2];
        #pragma unroll
        for (int mi = 0; mi < MI; ++mi) {
            unsigned ao = (unsigned)(((wm0 + mi*16 + a_row) * 40 + ks + a_col) * 2);
            ldm_x4(ah[mi], ub + SOFF + ao);
            ldm_x4(al[mi], ub + SOFF + AL_OFF + ao);
        }
        #pragma unroll
        for (int njp = 0; njp < NJ / 2; ++njp) {
            unsigned bo = (unsigned)(((wn0 + njp*16 + b_row) * 40 + ks + b_col) * 2);
            uint32_t t[4];
            ldm_x4(t, ub + SOFF + BH_OFF + bo);
            bh[njp*2][0] = t[0];
            bh[njp*2][1] = t[1];
            bh[njp*2+1][0] = t[2];
            bh[njp*2+1][1] = t[3];
            ldm_x4(t, ub + SOFF + BL_OFF + bo);
            bl[njp*2][0] = t[0];
            bl[njp*2][1] = t[1];
            bl[njp*2+1][0] = t[2];
            bl[njp*2+1][1] = t[3];
        }
        #pragma unroll
        for (int mi = 0; mi < MI; ++mi)
            #pragma unroll
            for (int nj = 0; nj < NJ; ++nj)
                mma16816(acc[mi][nj], ah[mi], bh[nj]);
        #pragma unroll
        for (int mi = 0; mi < MI; ++mi)
            #pragma unroll
            for (int nj = 0; nj < NJ; ++nj)
                mma16816(acc[mi][nj], ah[mi], bl[nj]);
        #pragma unroll
        for (int mi = 0; mi < MI; ++mi)
            #pragma unroll
            for (int nj = 0; nj < NJ; ++nj)
                mma16816(acc[mi][nj], al[mi], bh[nj]);
    }
}

template<int NK>
__device__ __forceinline__ void g_wait(int c)
{
    if (NK - c >= 3) cpa_wait<2>();
    else if (NK - c == 2) cpa_wait<1>();
    else cpa_wait<0>();
}

// EPI 0: fp32 C (+bias). EPI 1: bf16 hi/lo split outputs. EPI 2: mel transposed.
template<int MI, int NJ, int EPI, int N, int K>
__device__ void gemm_body(const __nv_bfloat16* Ahi, const __nv_bfloat16* Alo,
                          const __nv_bfloat16* Bhi, const __nv_bfloat16* Blo,
                          const float* bias, float* C,
                          __nv_bfloat16* Oh, __nv_bfloat16* Ol)
{
    constexpr int BM = 2 * MI * 16;
    constexpr int BN = 4 * NJ * 8;
    constexpr int NK = K / 32;
    static_assert(NK % 4 == 0, "NK must be divisible by 4");
    extern __shared__ __nv_bfloat16 dyn[];

    const int tid = threadIdx.x;
    const int warp = tid >> 5;
    const int lane = tid & 31;
    const int wm = warp & 1;
    const int wn = warp >> 1;
    const int m0b = blockIdx.y * BM;
    const int n0b = blockIdx.x * BN;
    const int wm0 = wm * MI * 16;
    const int wn0 = wn * NJ * 8;
    const unsigned ub = smaddr(dyn);

    float acc[MI][NJ][4];
    #pragma unroll
    for (int i = 0; i < MI; ++i)
        #pragma unroll
        for (int j = 0; j < NJ; ++j)
            #pragma unroll
            for (int c = 0; c < 4; ++c) acc[i][j][c] = 0.f;

    const int lr0 = tid >> 2;
    const int lc  = (tid & 3) * 8;
    const int a_row = lane & 15;
    const int a_col = (lane >> 4) * 8;
    const int b_row = (lane & 7) + ((lane >> 4) << 3);
    const int b_col = ((lane >> 3) & 1) * 8;

    g_load<BM,BN,K,0>(ub, Ahi, Alo, Bhi, Blo, m0b, n0b, 0,  lr0, lc);
    g_load<BM,BN,K,1>(ub, Ahi, Alo, Bhi, Blo, m0b, n0b, 32, lr0, lc);
    g_load<BM,BN,K,2>(ub, Ahi, Alo, Bhi, Blo, m0b, n0b, 64, lr0, lc);

    for (int c = 0; c < NK; c += 4) {
        g_wait<NK>(c);
        __syncthreads();
        if (c + 3 < NK) g_load<BM,BN,K,3>(ub, Ahi, Alo, Bhi, Blo, m0b, n0b, (c+3)*32, lr0, lc);
        g_comp<MI,NJ,0>(ub, acc, wm0, wn0, a_row, a_col, b_row, b_col);

        g_wait<NK>(c + 1);
        __syncthreads();
        if (c + 4 < NK) g_load<BM,BN,K,0>(ub, Ahi, Alo, Bhi, Blo, m0b, n0b, (c+4)*32, lr0, lc);
        g_comp<MI,NJ,1>(ub, acc, wm0, wn0, a_row, a_col, b_row, b_col);

        g_wait<NK>(c + 2);
        __syncthreads();
        if (c + 5 < NK) g_load<BM,BN,K,1>(ub, Ahi, Alo, Bhi, Blo, m0b, n0b, (c+5)*32, lr0, lc);
        g_comp<MI,NJ,2>(ub, acc, wm0, wn0, a_row, a_col, b_row, b_col);

        g_wait<NK>(c + 3);
        __syncthreads();
        if (c + 6 < NK) g_load<BM,BN,K,2>(ub, Ahi, Alo, Bhi, Blo, m0b, n0b, (c+6)*32, lr0, lc);
        g_comp<MI,NJ,3>(ub, acc, wm0, wn0, a_row, a_col, b_row, b_col);
    }

    const int g = lane >> 2;
    const int tg = lane & 3;
    #pragma unroll
    for (int mi = 0; mi < MI; ++mi)
        #pragma unroll
        for (int nj = 0; nj < NJ; ++nj) {
            int m = m0b + wm0 + mi * 16 + g;
            int n = n0b + wn0 + nj * 8 + tg * 2;
            float v0 = acc[mi][nj][0];
            float v1 = acc[mi][nj][1];
            float v2 = acc[mi][nj][2];
            float v3 = acc[mi][nj][3];
            if (EPI == 0) {
                if (bias) {
                    v0 += bias[n];
                    v1 += bias[n+1];
                    v2 += bias[n];
                    v3 += bias[n+1];
                }
                C[(size_t)m * N + n]       = v0;
                C[(size_t)m * N + n + 1]   = v1;
                C[(size_t)(m+8) * N + n]   = v2;
                C[(size_t)(m+8) * N + n+1] = v3;
            } else if (EPI == 1) {
                __nv_bfloat16 h0, h1, h2, h3, l0, l1, l2, l3;
                split2(v0, h0, l0);
                split2(v1, h1, l1);
                split2(v2, h2, l2);
                split2(v3, h3, l3);
                *(__nv_bfloat162*)(Oh + (size_t)m * N + n)       = __nv_bfloat162(h0, h1);
                *(__nv_bfloat162*)(Ol + (size_t)m * N + n)       = __nv_bfloat162(l0, l1);
                *(__nv_bfloat162*)(Oh + (size_t)(m+8) * N + n)   = __nv_bfloat162(h2, h3);
                *(__nv_bfloat162*)(Ol + (size_t)(m+8) * N + n)   = __nv_bfloat162(l2, l3);
            } else {
                float bn0 = (n < NMEL) ? bias[n] : 0.f;
                float bn1 = (n + 1 < NMEL) ? bias[n + 1] : 0.f;
                v0 += bn0;
                v1 += bn1;
                v2 += bn0;
                v3 += bn1;
                int bb = m >> 10;
                int t = m & 1023;
                int bb2 = (m + 8) >> 10;
                int t2 = (m + 8) & 1023;
                if (n < NMEL) {
                    C[(size_t)(bb*NMEL + n) * NT_SEQ + t] = v0;
                    C[(size_t)(bb2*NMEL + n) * NT_SEQ + t2] = v2;
                }
                if (n + 1 < NMEL) {
                    C[(size_t)(bb*NMEL + n+1) * NT_SEQ + t] = v1;
                    C[(size_t)(bb2*NMEL + n+1) * NT_SEQ + t2] = v3;
                }
            }
        }
}

// ---------------- conv / ln bodies ----------------
template<bool DO_GELU>
__device__ void conv_body(const float* in, const float* w, const float* bias, float* out)
{
    __shared__ float sm[10][DD];
    const int blk = blockIdx.x;
    const int b  = blk / (NT_SEQ / 8);
    const int t0 = (blk % (NT_SEQ / 8)) * 8;
    const float* inb = in + (size_t)b * NT_SEQ * DD;
    const int tid = threadIdx.x;

    for (int idx = tid; idx < 10 * DD; idx += 256) {
        int r = idx / DD;
        int c = idx % DD;
        int t = t0 - 1 + r;
        sm[r][c] = (t >= 0 && t < NT_SEQ) ? inb[(size_t)t*DD + c] : 0.f;
    }
    __syncthreads();

    const int cbase = tid * 4;
    const int g = cbase >> 6;
    float acc[4][8];
    #pragma unroll
    for (int cc = 0; cc < 4; ++cc) {
        float bb = bias[cbase + cc];
        #pragma unroll
        for (int tt = 0; tt < 8; ++tt) acc[cc][tt] = bb;
    }
    const float* wp = w + (size_t)cbase * 192;

    for (int ci = 0; ci < 64; ++ci) {
        float x[10];
        #pragma unroll
        for (int r = 0; r < 10; ++r) x[r] = sm[r][g*64 + ci];
        #pragma unroll
        for (int cc = 0; cc < 4; ++cc) {
            float w0 = wp[cc*192 + ci*3 + 0];
            float w1 = wp[cc*192 + ci*3 + 1];
            float w2 = wp[cc*192 + ci*3 + 2];
            #pragma unroll
            for (int tt = 0; tt < 8; ++tt)
                acc[cc][tt] += w0*x[tt] + w1*x[tt+1] + w2*x[tt+2];
        }
    }

    float* outb = out + (size_t)b * NT_SEQ * DD;
    #pragma unroll
    for (int tt = 0; tt < 8; ++tt) {
        float v0 = acc[0][tt];
        float v1 = acc[1][tt];
        float v2 = acc[2][tt];
        float v3 = acc[3][tt];
        if (DO_GELU) {
            v0 = 0.5f*v0*(1.f + erff(v0*0.70710678118654752f));
            v1 = 0.5f*v1*(1.f + erff(v1*0.70710678118654752f));
            v2 = 0.5f*v2*(1.f + erff(v2*0.70710678118654752f));
            v3 = 0.5f*v3*(1.f + erff(v3*0.70710678118654752f));
        }
        float4 o;
        o.x = v0;
        o.y = v1;
        o.z = v2;
        o.w = v3;
        *(float4*)(outb + (size_t)(t0+tt)*DD + cbase) = o;
    }
}

__device__ void ln_body(const float* in, const float* gam, const float* bet,
                        __nv_bfloat16* oh, __nv_bfloat16* ol)
{
    __shared__ float s1[8];
    __shared__ float s2[8];
    const int row = blockIdx.x;
    const int tid = threadIdx.x;
    const float4* x4 = (const float4*)(in + (size_t)row * DD);
    float4 v = x4[tid];
    float s = v.x + v.y + v.z + v.w;
    float q = v.x*v.x + v.y*v.y + v.z*v.z + v.w*v.w;
    #pragma unroll
    for (int o = 16; o > 0; o >>= 1) {
        s += __shfl_xor_sync(0xFFFFFFFFu, s, o);
        q += __shfl_xor_sync(0xFFFFFFFFu, q, o);
    }
    if ((tid & 31) == 0) {
        s1[tid >> 5] = s;
        s2[tid >> 5] = q;
    }
    __syncthreads();
    float ts = 0.f;
    float tq = 0.f;
    #pragma unroll
    for (int i = 0; i < 8; ++i) {
        ts += s1[i];
        tq += s2[i];
    }
    const float mu   = ts * (1.f / DD);
    const float var  = tq * (1.f / DD) - mu * mu;
    const float rstd = rsqrtf(var + 1e-5f);
    float4 g4 = ((const float4*)gam)[tid];
    float4 b4 = ((const float4*)bet)[tid];
    float y0 = (v.x - mu) * rstd * g4.x + b4.x;
    float y1 = (v.y - mu) * rstd * g4.y + b4.y;
    float y2 = (v.z - mu) * rstd * g4.z + b4.z;
    float y3 = (v.w - mu) * rstd * g4.w + b4.w;
    __nv_bfloat16 h0, h1, h2, h3, l0, l1, l2, l3;
    split2(y0, h0, l0);
    split2(y1, h1, l1);
    split2(y2, h2, l2);
    split2(y3, h3, l3);
    size_t o = (size_t)row * DD + tid * 4;
    ((__nv_bfloat162*)(oh + o))[0] = __nv_bfloat162(h0, h1);
    ((__nv_bfloat162*)(oh + o))[1] = __nv_bfloat162(h2, h3);
    ((__nv_bfloat162*)(ol + o))[0] = __nv_bfloat162(l0, l1);
    ((__nv_bfloat162*)(ol + o))[1] = __nv_bfloat162(l2, l3);
}

// ---------------- wrapper kernels ----------------
__global__ void k_split_Win(const float* W_in) { split_dir_body(W_in, g_WinD_h, g_WinD_l, DD*LL/4); }
__global__ void k_split_Wd(const float* Wd)    { split_dir_body(Wd, g_WdD_h, g_WdD_l, DD*LL/4); }
__global__ void k_split_llama(const float* x)  { split_dir_body(x, g_Lla_h, g_Lla_l, ROWS*LL/4); }
__global__ void k_split_Pdir(const float* P)   { split_dir_body(P, g_Pd_h, g_Pd_l, DD*DD/4); }

__global__ void k_trans_WinT(const float* W_in) { split_trans_body<false>(W_in, 0, g_WinT_h, g_WinT_l, DD, LL); }
__global__ void k_trans_PT(const float* P)      { split_trans_body<false>(P, 0, g_Pt_h, g_Pt_l, DD, DD); }
__global__ void k_trans_wpT()                   { split_trans_body<false>(g_wproj, 0, g_wpT_h, g_wpT_l, DD, DD); }
__global__ void k_trans_S(const float* mask)    { split_trans_body<true>(g_wprime, mask, g_S_h, g_S_l, DD, DD); }
__global__ void k_trans_uT()                    { split_trans_body<false>(g_u, 0, g_uT_h, g_uT_l, DD, DD); }
__global__ void k_trans_QT()                    { split_trans_body<false>(g_Qf, 0, g_QT_h, g_QT_l, DD, DD); }

__global__ void k_split_mel(const float* Wmel)
{
    int i = blockIdx.x * 256 + threadIdx.x;
    int r = i >> 10;
    float v = (r < NMEL) ? Wmel[(size_t)r * DD + (i & 1023)] : 0.f;
    __nv_bfloat16 h, l;
    split2(v, h, l);
    g_Wmel_h[i] = h;
    g_Wmel_l[i] = l;
}

__global__ __launch_bounds__(256) void k_gemm_wproj(const float* bd)
{ gemm_body<2,4,0,DD,LL>(g_WinD_h, g_WinD_l, g_WdD_h, g_WdD_l, bd, g_wproj, 0, 0); }

__global__ __launch_bounds__(256) void k_gemm_t1()
{ gemm_body<2,4,1,DD,DD>(g_Pt_h, g_Pt_l, g_wpT_h, g_wpT_l, 0, 0, g_t1s_h, g_t1s_l); }

__global__ __launch_bounds__(256) void k_gemm_wprime()
{ gemm_body<2,4,0,DD,DD>(g_t1s_h, g_t1s_l, g_Pt_h, g_Pt_l, 0, g_wprime, 0, 0); }

__global__ __launch_bounds__(256) void k_gemm_u()
{ gemm_body<2,4,0,DD,DD>(g_S_h, g_S_l, g_Pd_h, g_Pd_l, 0, g_u, 0, 0); }

__global__ __launch_bounds__(256) void k_gemm_Q()
{ gemm_body<2,4,0,DD,DD>(g_Pd_h, g_Pd_l, g_uT_h, g_uT_l, 0, g_Qf, 0, 0); }

__global__ __launch_bounds__(256) void k_gemm_WcT()
{ gemm_body<2,4,1,LL,DD>(g_QT_h, g_QT_l, g_WinT_h, g_WinT_l, 0, 0, g_WcTs_h, g_WcTs_l); }

__global__ __launch_bounds__(256) void k_gemm_fused()
{ gemm_body<2,4,0,DD,LL>(g_Lla_h, g_Lla_l, g_WcTs_h, g_WcTs_l, g_bvec, g_fused, 0, 0); }

__global__ __launch_bounds__(256) void k_gemm_mel(const float* bmel, float* out)
{ gemm_body<2,2,2,128,DD>(g_xn_h, g_xn_l, g_Wmel_h, g_Wmel_l, bmel, out, 0, 0); }

__global__ void k_bvec(const float* b_in)
{
    int e = blockIdx.x * blockDim.x + threadIdx.x;
    if (e >= DD) return;
    float s = 0.f;
    for (int d = 0; d < DD; ++d) s += b_in[d] * g_Qf[(size_t)d * DD + e];
    g_bvec[e] = s;
}

__global__ __launch_bounds__(256) void k_conv1(const float* w, const float* b)
{ conv_body<true>(g_fused, w, b, g_h1); }

__global__ __launch_bounds__(256) void k_conv2(const float* w, const float* b)
{ conv_body<false>(g_h1, w, b, g_h2); }

__global__ __launch_bounds__(256) void k_ln(const float* g, const float* b)
{ ln_body(g_h2, g, b, g_xn_h, g_xn_l); }

// ---------------- launch ----------------
extern "C" void kernel_launch(void* const* d_in, const int* in_sizes, int n_in,
                              void* d_out, int out_size)
{
    (void)in_sizes;
    (void)n_in;
    (void)out_size;
    const float* llama = (const float*)d_in[0];
    const float* W_in  = (const float*)d_in[2];
    const float* b_in  = (const float*)d_in[3];
    const float* P     = (const float*)d_in[4];
    const float* smask = (const float*)d_in[5];
    const float* Wd    = (const float*)d_in[6];
    const float* bd    = (const float*)d_in[7];
    const float* c1w   = (const float*)d_in[8];
    const float* c1b   = (const float*)d_in[9];
    const float* c2w   = (const float*)d_in[10];
    const float* c2b   = (const float*)d_in[11];
    const float* lng   = (const float*)d_in[12];
    const float* lnb   = (const float*)d_in[13];
    const float* Wmel  = (const float*)d_in[14];
    const float* bmel  = (const float*)d_in[15];
    float* out = (float*)d_out;

    // 4 stages * (2*BM + 2*BN) * 40 elems * 2B
    const int smem_64_128 = 4 * (128 + 256) * 40 * 2;   // 122880
    const int smem_64_64  = 4 * (128 + 128) * 40 * 2;   // 81920

    cudaFuncSetAttribute(k_gemm_wproj,  cudaFuncAttributeMaxDynamicSharedMemorySize, smem_64_128);
    cudaFuncSetAttribute(k_gemm_t1,     cudaFuncAttributeMaxDynamicSharedMemorySize, smem_64_128);
    cudaFuncSetAttribute(k_gemm_wprime, cudaFuncAttributeMaxDynamicSharedMemorySize, smem_64_128);
    cudaFuncSetAttribute(k_gemm_u,      cudaFuncAttributeMaxDynamicSharedMemorySize, smem_64_128);
    cudaFuncSetAttribute(k_gemm_Q,      cudaFuncAttributeMaxDynamicSharedMemorySize, smem_64_128);
    cudaFuncSetAttribute(k_gemm_WcT,    cudaFuncAttributeMaxDynamicSharedMemorySize, smem_64_128);
    cudaFuncSetAttribute(k_gemm_fused,  cudaFuncAttributeMaxDynamicSharedMemorySize, smem_64_128);
    cudaFuncSetAttribute(k_gemm_mel,    cudaFuncAttributeMaxDynamicSharedMemorySize, smem_64_64);

    dim3 tb(32, 8);

    // FROZEN launch order (round-12; known-good with the bench container).
    k_split_Win<<<DD*LL/4/256, 256>>>(W_in);
    k_split_Wd<<<DD*LL/4/256, 256>>>(Wd);
    k_trans_WinT<<<dim3(DD/32, LL/32), tb>>>(W_in);
    k_split_llama<<<ROWS*LL/4/256, 256>>>(llama);
    k_split_Pdir<<<DD*DD/4/256, 256>>>(P);
    k_trans_PT<<<dim3(DD/32, DD/32), tb>>>(P);
    k_split_mel<<<128*DD/256, 256>>>(Wmel);

    k_gemm_wproj<<<dim3(DD/128, DD/64), 256, smem_64_128>>>(bd);
    k_trans_wpT<<<dim3(DD/32, DD/32), tb>>>();
    k_gemm_t1<<<dim3(DD/128, DD/64), 256, smem_64_128>>>();
    k_gemm_wprime<<<dim3(DD/128, DD/64), 256, smem_64_128>>>();
    k_trans_S<<<dim3(DD/32, DD/32), tb>>>(smask);
    k_gemm_u<<<dim3(DD/128, DD/64), 256, smem_64_128>>>();
    k_trans_uT<<<dim3(DD/32, DD/32), tb>>>();
    k_gemm_Q<<<dim3(DD/128, DD/64), 256, smem_64_128>>>();
    k_trans_QT<<<dim3(DD/32, DD/32), tb>>>();
    k_bvec<<<DD/256, 256>>>(b_in);
    k_gemm_WcT<<<dim3(LL/128, DD/64), 256, smem_64_128>>>();
    k_gemm_fused<<<dim3(DD/128, ROWS/64), 256, smem_64_128>>>();

    k_conv1<<<NB * (NT_SEQ/8), 256>>>(c1w, c1b);
    k_conv2<<<NB * (NT_SEQ/8), 256>>>(c2w, c2b);
    k_ln<<<ROWS, 256>>>(lng, lnb);
    k_gemm_mel<<<dim3(2, ROWS/64), 256, smem_64_64>>>(bmel, out);
}

// round 15
// speedup vs baseline: 1.0565x; 1.0563x over previous
#include <cuda_runtime.h>
#include <cuda_fp16.h>
#include <stdint.h>
#include <math.h>

#define DD 1024
#define LL 3072
#define NMEL 100
#define NB 4
#define NT_SEQ 1024
#define ROWS (NB*NT_SEQ)

// ---------------- fp32 scratch ----------------
__device__ float g_wproj[DD*DD];
__device__ float g_wprime[DD*DD];
__device__ float g_u[DD*DD];
__device__ float g_Qf[DD*DD];
__device__ float g_fused[ROWS*DD];
__device__ float g_h1[ROWS*DD];
__device__ float g_h2[ROWS*DD];
__device__ float g_bvec[DD];

// ---------------- fp16 split scratch ----------------
__device__ __half g_WinD_h[DD*LL];
__device__ __half g_WinD_l[DD*LL];
__device__ __half g_WdD_h[DD*LL];
__device__ __half g_WdD_l[DD*LL];
__device__ __half g_WinT_h[LL*DD];
__device__ __half g_WinT_l[LL*DD];
__device__ __half g_Lla_h[ROWS*LL];
__device__ __half g_Lla_l[ROWS*LL];
__device__ __half g_Pd_h[DD*DD];
__device__ __half g_Pd_l[DD*DD];
__device__ __half g_Pt_h[DD*DD];
__device__ __half g_Pt_l[DD*DD];
__device__ __half g_wpT_h[DD*DD];
__device__ __half g_wpT_l[DD*DD];
__device__ __half g_t1s_h[DD*DD];
__device__ __half g_t1s_l[DD*DD];
__device__ __half g_S_h[DD*DD];
__device__ __half g_S_l[DD*DD];
__device__ __half g_uT_h[DD*DD];
__device__ __half g_uT_l[DD*DD];
__device__ __half g_QT_h[DD*DD];
__device__ __half g_QT_l[DD*DD];
__device__ __half g_WcTs_h[DD*LL];
__device__ __half g_WcTs_l[DD*LL];
__device__ __half g_xn_h[ROWS*DD];
__device__ __half g_xn_l[ROWS*DD];
__device__ __half g_Wmel_h[128*DD];
__device__ __half g_Wmel_l[128*DD];

// ---------------- device helpers ----------------
__device__ __forceinline__ void split2(float x, __half& h, __half& l) {
    h = __float2half_rn(x);
    l = __float2half_rn(x - __half2float(h));
}

__device__ __forceinline__ unsigned smaddr(const void* p) {
    return (unsigned)__cvta_generic_to_shared(p);
}

__device__ __forceinline__ void ldm_x4(uint32_t* r, unsigned a) {
    asm volatile("ldmatrix.sync.aligned.m8n8.x4.shared.b16 {%0,%1,%2,%3}, [%4];"
        : "=r"(r[0]), "=r"(r[1]), "=r"(r[2]), "=r"(r[3]) : "r"(a));
}

__device__ __forceinline__ void mma16816(float* d, const uint32_t* a, const uint32_t* b) {
    asm volatile("mma.sync.aligned.m16n8k16.row.col.f32.f16.f16.f32 "
        "{%0,%1,%2,%3}, {%4,%5,%6,%7}, {%8,%9}, {%0,%1,%2,%3};"
        : "+f"(d[0]), "+f"(d[1]), "+f"(d[2]), "+f"(d[3])
        : "r"(a[0]), "r"(a[1]), "r"(a[2]), "r"(a[3]), "r"(b[0]), "r"(b[1]));
}

__device__ __forceinline__ void cpa16(unsigned sm, const void* g) {
    asm volatile("cp.async.cg.shared.global [%0], [%1], 16;" :: "r"(sm), "l"(g));
}

__device__ __forceinline__ void cpa_commit() {
    asm volatile("cp.async.commit_group;");
}

template<int W>
__device__ __forceinline__ void cpa_wait() {
    asm volatile("cp.async.wait_group %0;" :: "n"(W));
}

// ---------------- convert bodies ----------------
__device__ void split_dir_body(const float* in, __half* hi, __half* lo, int n4)
{
    int i = blockIdx.x * blockDim.x + threadIdx.x;
    if (i >= n4) return;
    float4 v = ((const float4*)in)[i];
    __half h0, h1, h2, h3, l0, l1, l2, l3;
    split2(v.x, h0, l0);
    split2(v.y, h1, l1);
    split2(v.z, h2, l2);
    split2(v.w, h3, l3);
    ((__half2*)hi)[2*i+0] = __halves2half2(h0, h1);
    ((__half2*)hi)[2*i+1] = __halves2half2(h2, h3);
    ((__half2*)lo)[2*i+0] = __halves2half2(l0, l1);
    ((__half2*)lo)[2*i+1] = __halves2half2(l2, l3);
}

template<bool SIG>
__device__ void split_trans_body(const float* in, const float* mask,
                                 __half* hi, __half* lo, int P_, int Q_)
{
    __shared__ float t[32][33];
    int p0 = blockIdx.x * 32;
    int q0 = blockIdx.y * 32;
    int tx = threadIdx.x;
    int ty = threadIdx.y;
    #pragma unroll
    for (int dy = 0; dy < 32; dy += 8) {
        size_t idx = (size_t)(p0 + ty + dy) * Q_ + q0 + tx;
        float v = in[idx];
        if (SIG) v *= 1.f / (1.f + __expf(-mask[idx]));
        t[ty + dy][tx] = v;
    }
    __syncthreads();
    #pragma unroll
    for (int dy = 0; dy < 32; dy += 8) {
        float v = t[tx][ty + dy];
        __half h, l;
        split2(v, h, l);
        size_t o = (size_t)(q0 + ty + dy) * P_ + p0 + tx;
        hi[o] = h;
        lo[o] = l;
    }
}

// ---------------- templated-stage split-fp16 mma.sync GEMM ----------------
// 4-stage cp.async ring; compile-time stage indices.
// PASSES==3: hh + hl + lh.  PASSES==2: hh + hl (drops al*bh; al ldmatrix skipped).

template<int BM, int BN, int K, int ST>
__device__ __forceinline__ void g_load(unsigned ub,
    const __half* Ahi, const __half* Alo,
    const __half* Bhi, const __half* Blo,
    int m0b, int n0b, int k0, int lr0, int lc)
{
    constexpr int STRIDE = (2*BM + 2*BN) * 40;
    constexpr unsigned SOFF = (unsigned)(ST * STRIDE * 2);
    #pragma unroll
    for (int h = 0; h < BM / 64; ++h) {
        int r = lr0 + h * 64;
        size_t ga = (size_t)(m0b + r) * K + k0 + lc;
        cpa16(ub + SOFF + (unsigned)((r * 40 + lc) * 2), Ahi + ga);
        cpa16(ub + SOFF + (unsigned)((BM*40 + r * 40 + lc) * 2), Alo + ga);
    }
    #pragma unroll
    for (int h = 0; h < BN / 64; ++h) {
        int r = lr0 + h * 64;
        size_t gb = (size_t)(n0b + r) * K + k0 + lc;
        cpa16(ub + SOFF + (unsigned)((2*BM*40 + r * 40 + lc) * 2), Bhi + gb);
        cpa16(ub + SOFF + (unsigned)((2*BM*40 + BN*40 + r * 40 + lc) * 2), Blo + gb);
    }
    cpa_commit();
}

template<int MI, int NJ, int ST, int PASSES>
__device__ __forceinline__ void g_comp(unsigned ub, float (&acc)[MI][NJ][4],
    int wm0, int wn0, int a_row, int a_col, int b_row, int b_col)
{
    constexpr int BM = 2 * MI * 16;
    constexpr int BN = 4 * NJ * 8;
    constexpr int STRIDE = (2*BM + 2*BN) * 40;
    constexpr unsigned SOFF = (unsigned)(ST * STRIDE * 2);
    constexpr unsigned AL_OFF = (unsigned)(BM * 40 * 2);
    constexpr unsigned BH_OFF = (unsigned)(2 * BM * 40 * 2);
    constexpr unsigned BL_OFF = (unsigned)((2 * BM + BN) * 40 * 2);

    #pragma unroll
    for (int ks = 0; ks < 32; ks += 16) {
        uint32_t ah[MI][4];
        uint32_t al[MI][4];
        uint32_t bh[NJ][2];
        uint32_t bl[NJ][2];
        #pragma unroll
        for (int mi = 0; mi < MI; ++mi) {
            unsigned ao = (unsigned)(((wm0 + mi*16 + a_row) * 40 + ks + a_col) * 2);
            ldm_x4(ah[mi], ub + SOFF + ao);
            if (PASSES == 3) ldm_x4(al[mi], ub + SOFF + AL_OFF + ao);
        }
        #pragma unroll
        for (int njp = 0; njp < NJ / 2; ++njp) {
            unsigned bo = (unsigned)(((wn0 + njp*16 + b_row) * 40 + ks + b_col) * 2);
            uint32_t t[4];
            ldm_x4(t, ub + SOFF + BH_OFF + bo);
            bh[njp*2][0] = t[0];
            bh[njp*2][1] = t[1];
            bh[njp*2+1][0] = t[2];
            bh[njp*2+1][1] = t[3];
            ldm_x4(t, ub + SOFF + BL_OFF + bo);
            bl[njp*2][0] = t[0];
            bl[njp*2][1] = t[1];
            bl[njp*2+1][0] = t[2];
            bl[njp*2+1][1] = t[3];
        }
        #pragma unroll
        for (int mi = 0; mi < MI; ++mi)
            #pragma unroll
            for (int nj = 0; nj < NJ; ++nj)
                mma16816(acc[mi][nj], ah[mi], bh[nj]);
        #pragma unroll
        for (int mi = 0; mi < MI; ++mi)
            #pragma unroll
            for (int nj = 0; nj < NJ; ++nj)
                mma16816(acc[mi][nj], ah[mi], bl[nj]);
        if (PASSES == 3) {
            #pragma unroll
            for (int mi = 0; mi < MI; ++mi)
                #pragma unroll
                for (int nj = 0; nj < NJ; ++nj)
                    mma16816(acc[mi][nj], al[mi], bh[nj]);
        }
    }
}

template<int NK>
__device__ __forceinline__ void g_wait(int c)
{
    if (NK - c >= 3) cpa_wait<2>();
    else if (NK - c == 2) cpa_wait<1>();
    else cpa_wait<0>();
}

// EPI 0: fp32 C (+bias). EPI 1: fp16 hi/lo split outputs. EPI 2: mel transposed.
template<int MI, int NJ, int EPI, int N, int K, int PASSES>
__device__ void gemm_body(const __half* Ahi, const __half* Alo,
                          const __half* Bhi, const __half* Blo,
                          const float* bias, float* C,
                          __half* Oh, __half* Ol)
{
    constexpr int BM = 2 * MI * 16;
    constexpr int BN = 4 * NJ * 8;
    constexpr int NK = K / 32;
    static_assert(NK % 4 == 0, "NK must be divisible by 4");
    extern __shared__ __half dyn[];

    const int tid = threadIdx.x;
    const int warp = tid >> 5;
    const int lane = tid & 31;
    const int wm = warp & 1;
    const int wn = warp >> 1;
    const int m0b = blockIdx.y * BM;
    const int n0b = blockIdx.x * BN;
    const int wm0 = wm * MI * 16;
    const int wn0 = wn * NJ * 8;
    const unsigned ub = smaddr(dyn);

    float acc[MI][NJ][4];
    #pragma unroll
    for (int i = 0; i < MI; ++i)
        #pragma unroll
        for (int j = 0; j < NJ; ++j)
            #pragma unroll
            for (int c = 0; c < 4; ++c) acc[i][j][c] = 0.f;

    const int lr0 = tid >> 2;
    const int lc  = (tid & 3) * 8;
    const int a_row = lane & 15;
    const int a_col = (lane >> 4) * 8;
    const int b_row = (lane & 7) + ((lane >> 4) << 3);
    const int b_col = ((lane >> 3) & 1) * 8;

    g_load<BM,BN,K,0>(ub, Ahi, Alo, Bhi, Blo, m0b, n0b, 0,  lr0, lc);
    g_load<BM,BN,K,1>(ub, Ahi, Alo, Bhi, Blo, m0b, n0b, 32, lr0, lc);
    g_load<BM,BN,K,2>(ub, Ahi, Alo, Bhi, Blo, m0b, n0b, 64, lr0, lc);

    for (int c = 0; c < NK; c += 4) {
        g_wait<NK>(c);
        __syncthreads();
        if (c + 3 < NK) g_load<BM,BN,K,3>(ub, Ahi, Alo, Bhi, Blo, m0b, n0b, (c+3)*32, lr0, lc);
        g_comp<MI,NJ,0,PASSES>(ub, acc, wm0, wn0, a_row, a_col, b_row, b_col);

        g_wait<NK>(c + 1);
        __syncthreads();
        if (c + 4 < NK) g_load<BM,BN,K,0>(ub, Ahi, Alo, Bhi, Blo, m0b, n0b, (c+4)*32, lr0, lc);
        g_comp<MI,NJ,1,PASSES>(ub, acc, wm0, wn0, a_row, a_col, b_row, b_col);

        g_wait<NK>(c + 2);
        __syncthreads();
        if (c + 5 < NK) g_load<BM,BN,K,1>(ub, Ahi, Alo, Bhi, Blo, m0b, n0b, (c+5)*32, lr0, lc);
        g_comp<MI,NJ,2,PASSES>(ub, acc, wm0, wn0, a_row, a_col, b_row, b_col);

        g_wait<NK>(c + 3);
        __syncthreads();
        if (c + 6 < NK) g_load<BM,BN,K,2>(ub, Ahi, Alo, Bhi, Blo, m0b, n0b, (c+6)*32, lr0, lc);
        g_comp<MI,NJ,3,PASSES>(ub, acc, wm0, wn0, a_row, a_col, b_row, b_col);
    }

    const int g = lane >> 2;
    const int tg = lane & 3;
    #pragma unroll
    for (int mi = 0; mi < MI; ++mi)
        #pragma unroll
        for (int nj = 0; nj < NJ; ++nj) {
            int m = m0b + wm0 + mi * 16 + g;
            int n = n0b + wn0 + nj * 8 + tg * 2;
            float v0 = acc[mi][nj][0];
            float v1 = acc[mi][nj][1];
            float v2 = acc[mi][nj][2];
            float v3 = acc[mi][nj][3];
            if (EPI == 0) {
                if (bias) {
                    v0 += bias[n];
                    v1 += bias[n+1];
                    v2 += bias[n];
                    v3 += bias[n+1];
                }
                C[(size_t)m * N + n]       = v0;
                C[(size_t)m * N + n + 1]   = v1;
                C[(size_t)(m+8) * N + n]   = v2;
                C[(size_t)(m+8) * N + n+1] = v3;
            } else if (EPI == 1) {
                __half h0, h1, h2, h3, l0, l1, l2, l3;
                split2(v0, h0, l0);
                split2(v1, h1, l1);
                split2(v2, h2, l2);
                split2(v3, h3, l3);
                *(__half2*)(Oh + (size_t)m * N + n)       = __halves2half2(h0, h1);
                *(__half2*)(Ol + (size_t)m * N + n)       = __halves2half2(l0, l1);
                *(__half2*)(Oh + (size_t)(m+8) * N + n)   = __halves2half2(h2, h3);
                *(__half2*)(Ol + (size_t)(m+8) * N + n)   = __halves2half2(l2, l3);
            } else {
                float bn0 = (n < NMEL) ? bias[n] : 0.f;
                float bn1 = (n + 1 < NMEL) ? bias[n + 1] : 0.f;
                v0 += bn0;
                v1 += bn1;
                v2 += bn0;
                v3 += bn1;
                int bb = m >> 10;
                int t = m & 1023;
                int bb2 = (m + 8) >> 10;
                int t2 = (m + 8) & 1023;
                if (n < NMEL) {
                    C[(size_t)(bb*NMEL + n) * NT_SEQ + t] = v0;
                    C[(size_t)(bb2*NMEL + n) * NT_SEQ + t2] = v2;
                }
                if (n + 1 < NMEL) {
                    C[(size_t)(bb*NMEL + n+1) * NT_SEQ + t] = v1;
                    C[(size_t)(bb2*NMEL + n+1) * NT_SEQ + t2] = v3;
                }
            }
        }
}

// ---------------- conv / ln bodies ----------------
template<bool DO_GELU>
__device__ void conv_body(const float* in, const float* w, const float* bias, float* out)
{
    __shared__ float sm[10][DD];
    const int blk = blockIdx.x;
    const int b  = blk / (NT_SEQ / 8);
    const int t0 = (blk % (NT_SEQ / 8)) * 8;
    const float* inb = in + (size_t)b * NT_SEQ * DD;
    const int tid = threadIdx.x;

    for (int idx = tid; idx < 10 * DD; idx += 256) {
        int r = idx / DD;
        int c = idx % DD;
        int t = t0 - 1 + r;
        sm[r][c] = (t >= 0 && t < NT_SEQ) ? inb[(size_t)t*DD + c] : 0.f;
    }
    __syncthreads();

    const int cbase = tid * 4;
    const int g = cbase >> 6;
    float acc[4][8];
    #pragma unroll
    for (int cc = 0; cc < 4; ++cc) {
        float bb = bias[cbase + cc];
        #pragma unroll
        for (int tt = 0; tt < 8; ++tt) acc[cc][tt] = bb;
    }
    const float* wp = w + (size_t)cbase * 192;

    for (int ci = 0; ci < 64; ++ci) {
        float x[10];
        #pragma unroll
        for (int r = 0; r < 10; ++r) x[r] = sm[r][g*64 + ci];
        #pragma unroll
        for (int cc = 0; cc < 4; ++cc) {
            float w0 = wp[cc*192 + ci*3 + 0];
            float w1 = wp[cc*192 + ci*3 + 1];
            float w2 = wp[cc*192 + ci*3 + 2];
            #pragma unroll
            for (int tt = 0; tt < 8; ++tt)
                acc[cc][tt] += w0*x[tt] + w1*x[tt+1] + w2*x[tt+2];
        }
    }

    float* outb = out + (size_t)b * NT_SEQ * DD;
    #pragma unroll
    for (int tt = 0; tt < 8; ++tt) {
        float v0 = acc[0][tt];
        float v1 = acc[1][tt];
        float v2 = acc[2][tt];
        float v3 = acc[3][tt];
        if (DO_GELU) {
            v0 = 0.5f*v0*(1.f + erff(v0*0.70710678118654752f));
            v1 = 0.5f*v1*(1.f + erff(v1*0.70710678118654752f));
            v2 = 0.5f*v2*(1.f + erff(v2*0.70710678118654752f));
            v3 = 0.5f*v3*(1.f + erff(v3*0.70710678118654752f));
        }
        float4 o;
        o.x = v0;
        o.y = v1;
        o.z = v2;
        o.w = v3;
        *(float4*)(outb + (size_t)(t0+tt)*DD + cbase) = o;
    }
}

__device__ void ln_body(const float* in, const float* gam, const float* bet,
                        __half* oh, __half* ol)
{
    __shared__ float s1[8];
    __shared__ float s2[8];
    const int row = blockIdx.x;
    const int tid = threadIdx.x;
    const float4* x4 = (const float4*)(in + (size_t)row * DD);
    float4 v = x4[tid];
    float s = v.x + v.y + v.z + v.w;
    float q = v.x*v.x + v.y*v.y + v.z*v.z + v.w*v.w;
    #pragma unroll
    for (int o = 16; o > 0; o >>= 1) {
        s += __shfl_xor_sync(0xFFFFFFFFu, s, o);
        q += __shfl_xor_sync(0xFFFFFFFFu, q, o);
    }
    if ((tid & 31) == 0) {
        s1[tid >> 5] = s;
        s2[tid >> 5] = q;
    }
    __syncthreads();
    float ts = 0.f;
    float tq = 0.f;
    #pragma unroll
    for (int i = 0; i < 8; ++i) {
        ts += s1[i];
        tq += s2[i];
    }
    const float mu   = ts * (1.f / DD);
    const float var  = tq * (1.f / DD) - mu * mu;
    const float rstd = rsqrtf(var + 1e-5f);
    float4 g4 = ((const float4*)gam)[tid];
    float4 b4 = ((const float4*)bet)[tid];
    float y0 = (v.x - mu) * rstd * g4.x + b4.x;
    float y1 = (v.y - mu) * rstd * g4.y + b4.y;
    float y2 = (v.z - mu) * rstd * g4.z + b4.z;
    float y3 = (v.w - mu) * rstd * g4.w + b4.w;
    __half h0, h1, h2, h3, l0, l1, l2, l3;
    split2(y0, h0, l0);
    split2(y1, h1, l1);
    split2(y2, h2, l2);
    split2(y3, h3, l3);
    size_t o = (size_t)row * DD + tid * 4;
    ((__half2*)(oh + o))[0] = __halves2half2(h0, h1);
    ((__half2*)(oh + o))[1] = __halves2half2(h2, h3);
    ((__half2*)(ol + o))[0] = __halves2half2(l0, l1);
    ((__half2*)(ol + o))[1] = __halves2half2(l2, l3);
}

// ---------------- wrapper kernels ----------------
__global__ void k_split_Win(const float* W_in) { split_dir_body(W_in, g_WinD_h, g_WinD_l, DD*LL/4); }
__global__ void k_split_Wd(const float* Wd)    { split_dir_body(Wd, g_WdD_h, g_WdD_l, DD*LL/4); }
__global__ void k_split_llama(const float* x)  { split_dir_body(x, g_Lla_h, g_Lla_l, ROWS*LL/4); }
__global__ void k_split_Pdir(const float* P)   { split_dir_body(P, g_Pd_h, g_Pd_l, DD*DD/4); }

__global__ void k_trans_WinT(const float* W_in) { split_trans_body<false>(W_in, 0, g_WinT_h, g_WinT_l, DD, LL); }
__global__ void k_trans_PT(const float* P)      { split_trans_body<false>(P, 0, g_Pt_h, g_Pt_l, DD, DD); }
__global__ void k_trans_wpT()                   { split_trans_body<false>(g_wproj, 0, g_wpT_h, g_wpT_l, DD, DD); }
__global__ void k_trans_S(const float* mask)    { split_trans_body<true>(g_wprime, mask, g_S_h, g_S_l, DD, DD); }
__global__ void k_trans_uT()                    { split_trans_body<false>(g_u, 0, g_uT_h, g_uT_l, DD, DD); }
__global__ void k_trans_QT()                    { split_trans_body<false>(g_Qf, 0, g_QT_h, g_QT_l, DD, DD); }

__global__ void k_split_mel(const float* Wmel)
{
    int i = blockIdx.x * 256 + threadIdx.x;
    int r = i >> 10;
    float v = (r < NMEL) ? Wmel[(size_t)r * DD + (i & 1023)] : 0.f;
    __half h, l;
    split2(v, h, l);
    g_Wmel_h[i] = h;
    g_Wmel_l[i] = l;
}

__global__ __launch_bounds__(256) void k_gemm_wproj(const float* bd)
{ gemm_body<2,4,0,DD,LL,3>(g_WinD_h, g_WinD_l, g_WdD_h, g_WdD_l, bd, g_wproj, 0, 0); }

__global__ __launch_bounds__(256) void k_gemm_t1()
{ gemm_body<2,4,1,DD,DD,3>(g_Pt_h, g_Pt_l, g_wpT_h, g_wpT_l, 0, 0, g_t1s_h, g_t1s_l); }

__global__ __launch_bounds__(256) void k_gemm_wprime()
{ gemm_body<2,4,0,DD,DD,3>(g_t1s_h, g_t1s_l, g_Pt_h, g_Pt_l, 0, g_wprime, 0, 0); }

__global__ __launch_bounds__(256) void k_gemm_u()
{ gemm_body<2,4,0,DD,DD,3>(g_S_h, g_S_l, g_Pd_h, g_Pd_l, 0, g_u, 0, 0); }

__global__ __launch_bounds__(256) void k_gemm_Q()
{ gemm_body<2,4,0,DD,DD,3>(g_Pd_h, g_Pd_l, g_uT_h, g_uT_l, 0, g_Qf, 0, 0); }

__global__ __launch_bounds__(256) void k_gemm_WcT()
{ gemm_body<2,4,1,LL,DD,3>(g_QT_h, g_QT_l, g_WinT_h, g_WinT_l, 0, 0, g_WcTs_h, g_WcTs_l); }

__global__ __launch_bounds__(256) void k_gemm_fused()
{ gemm_body<2,4,0,DD,LL,2>(g_Lla_h, g_Lla_l, g_WcTs_h, g_WcTs_l, g_bvec, g_fused, 0, 0); }

__global__ __launch_bounds__(256) void k_gemm_mel(const float* bmel, float* out)
{ gemm_body<2,2,2,128,DD,3>(g_xn_h, g_xn_l, g_Wmel_h, g_Wmel_l, bmel, out, 0, 0); }

// bvec[e] = sum_d b_in[d] * Q[d,e] — 16 blocks, 4 partials per e, smem reduce.
__global__ __launch_bounds__(256) void k_bvec(const float* b_in)
{
    __shared__ float red[4][64];
    int e = blockIdx.x * 64 + (threadIdx.x & 63);
    int part = threadIdx.x >> 6;              // 0..3
    float s = 0.f;
    for (int d = part * 256; d < part * 256 + 256; ++d)
        s += b_in[d] * g_Qf[(size_t)d * DD + e];
    red[part][threadIdx.x & 63] = s;
    __syncthreads();
    if (part == 0)
        g_bvec[e] = red[0][threadIdx.x] + red[1][threadIdx.x]
                  + red[2][threadIdx.x] + red[3][threadIdx.x];
}

__global__ __launch_bounds__(256) void k_conv1(const float* w, const float* b)
{ conv_body<true>(g_fused, w, b, g_h1); }

__global__ __launch_bounds__(256) void k_conv2(const float* w, const float* b)
{ conv_body<false>(g_h1, w, b, g_h2); }

__global__ __launch_bounds__(256) void k_ln(const float* g, const float* b)
{ ln_body(g_h2, g, b, g_xn_h, g_xn_l); }

// ---------------- launch ----------------
extern "C" void kernel_launch(void* const* d_in, const int* in_sizes, int n_in,
                              void* d_out, int out_size)
{
    (void)in_sizes;
    (void)n_in;
    (void)out_size;
    const float* llama = (const float*)d_in[0];
    const float* W_in  = (const float*)d_in[2];
    const float* b_in  = (const float*)d_in[3];
    const float* P     = (const float*)d_in[4];
    const float* smask = (const float*)d_in[5];
    const float* Wd    = (const float*)d_in[6];
    const float* bd    = (const float*)d_in[7];
    const float* c1w   = (const float*)d_in[8];
    const float* c1b   = (const float*)d_in[9];
    const float* c2w   = (const float*)d_in[10];
    const float* c2b   = (const float*)d_in[11];
    const float* lng   = (const float*)d_in[12];
    const float* lnb   = (const float*)d_in[13];
    const float* Wmel  = (const float*)d_in[14];
    const float* bmel  = (const float*)d_in[15];
    float* out = (float*)d_out;

    // 4 stages * (2*BM + 2*BN) * 40 elems * 2B
    const int smem_64_128 = 4 * (128 + 256) * 40 * 2;   // 122880
    const int smem_64_64  = 4 * (128 + 128) * 40 * 2;   // 81920

    cudaFuncSetAttribute(k_gemm_wproj,  cudaFuncAttributeMaxDynamicSharedMemorySize, smem_64_128);
    cudaFuncSetAttribute(k_gemm_t1,     cudaFuncAttributeMaxDynamicSharedMemorySize, smem_64_128);
    cudaFuncSetAttribute(k_gemm_wprime, cudaFuncAttributeMaxDynamicSharedMemorySize, smem_64_128);
    cudaFuncSetAttribute(k_gemm_u,      cudaFuncAttributeMaxDynamicSharedMemorySize, smem_64_128);
    cudaFuncSetAttribute(k_gemm_Q,      cudaFuncAttributeMaxDynamicSharedMemorySize, smem_64_128);
    cudaFuncSetAttribute(k_gemm_WcT,    cudaFuncAttributeMaxDynamicSharedMemorySize, smem_64_128);
    cudaFuncSetAttribute(k_gemm_fused,  cudaFuncAttributeMaxDynamicSharedMemorySize, smem_64_128);
    cudaFuncSetAttribute(k_gemm_mel,    cudaFuncAttributeMaxDynamicSharedMemorySize, smem_64_64);

    dim3 tb(32, 8);

    // FROZEN launch order (round-12; known-good with the bench container).
    k_split_Win<<<DD*LL/4/256, 256>>>(W_in);
    k_split_Wd<<<DD*LL/4/256, 256>>>(Wd);
    k_trans_WinT<<<dim3(DD/32, LL/32), tb>>>(W_in);
    k_split_llama<<<ROWS*LL/4/256, 256>>>(llama);
    k_split_Pdir<<<DD*DD/4/256, 256>>>(P);
    k_trans_PT<<<dim3(DD/32, DD/32), tb>>>(P);
    k_split_mel<<<128*DD/256, 256>>>(Wmel);

    k_gemm_wproj<<<dim3(DD/128, DD/64), 256, smem_64_128>>>(bd);
    k_trans_wpT<<<dim3(DD/32, DD/32), tb>>>();
    k_gemm_t1<<<dim3(DD/128, DD/64), 256, smem_64_128>>>();
    k_gemm_wprime<<<dim3(DD/128, DD/64), 256, smem_64_128>>>();
    k_trans_S<<<dim3(DD/32, DD/32), tb>>>(smask);
    k_gemm_u<<<dim3(DD/128, DD/64), 256, smem_64_128>>>();
    k_trans_uT<<<dim3(DD/32, DD/32), tb>>>();
    k_gemm_Q<<<dim3(DD/128, DD/64), 256, smem_64_128>>>();
    k_trans_QT<<<dim3(DD/32, DD/32), tb>>>();
    k_bvec<<<DD/64, 256>>>(b_in);
    k_gemm_WcT<<<dim3(LL/128, DD/64), 256, smem_64_128>>>();
    k_gemm_fused<<<dim3(DD/128, ROWS/64), 256, smem_64_128>>>();

    k_conv1<<<NB * (NT_SEQ/8), 256>>>(c1w, c1b);
    k_conv2<<<NB * (NT_SEQ/8), 256>>>(c2w, c2b);
    k_ln<<<ROWS, 256>>>(lng, lnb);
    k_gemm_mel<<<dim3(2, ROWS/64), 256, smem_64_64>>>(bmel, out);
}

// round 17
// speedup vs baseline: 1.1591x; 1.0971x over previous
#include <cuda_runtime.h>
#include <cuda_fp16.h>
#include <stdint.h>
#include <math.h>

#define DD 1024
#define LL 3072
#define NMEL 100
#define NB 4
#define NT_SEQ 1024
#define ROWS (NB*NT_SEQ)

// ---------------- fp32 scratch ----------------
__device__ float g_wproj[DD*DD];
__device__ float g_wprime[DD*DD];
__device__ float g_u[DD*DD];
__device__ float g_Qf[DD*DD];
__device__ float g_fused[ROWS*DD];
__device__ float g_h1[ROWS*DD];
__device__ float g_h2[ROWS*DD];
__device__ float g_bvec[DD];

// ---------------- fp16 split scratch ----------------
__device__ __half g_WinD_h[DD*LL];
__device__ __half g_WdD_h[DD*LL];
__device__ __half g_WdD_l[DD*LL];
__device__ __half g_WinT_h[LL*DD];
__device__ __half g_WinT_l[LL*DD];
__device__ __half g_Lla_h[ROWS*LL];
__device__ __half g_Pd_h[DD*DD];
__device__ __half g_Pd_l[DD*DD];
__device__ __half g_Pt_h[DD*DD];
__device__ __half g_Pt_l[DD*DD];
__device__ __half g_wpT_h[DD*DD];
__device__ __half g_wpT_l[DD*DD];
__device__ __half g_t1s_h[DD*DD];
__device__ __half g_S_h[DD*DD];
__device__ __half g_uT_h[DD*DD];
__device__ __half g_uT_l[DD*DD];
__device__ __half g_QT_h[DD*DD];
__device__ __half g_WcTs_h[DD*LL];
__device__ __half g_WcTs_l[DD*LL];
__device__ __half g_xn_h[ROWS*DD];
__device__ __half g_Wmel_h[128*DD];
__device__ __half g_Wmel_l[128*DD];

// ---------------- device helpers ----------------
__device__ __forceinline__ void split2(float x, __half& h, __half& l) {
    h = __float2half_rn(x);
    l = __float2half_rn(x - __half2float(h));
}

__device__ __forceinline__ unsigned smaddr(const void* p) {
    return (unsigned)__cvta_generic_to_shared(p);
}

__device__ __forceinline__ void ldm_x4(uint32_t* r, unsigned a) {
    asm volatile("ldmatrix.sync.aligned.m8n8.x4.shared.b16 {%0,%1,%2,%3}, [%4];"
        : "=r"(r[0]), "=r"(r[1]), "=r"(r[2]), "=r"(r[3]) : "r"(a));
}

__device__ __forceinline__ void mma16816(float* d, const uint32_t* a, const uint32_t* b) {
    asm volatile("mma.sync.aligned.m16n8k16.row.col.f32.f16.f16.f32 "
        "{%0,%1,%2,%3}, {%4,%5,%6,%7}, {%8,%9}, {%0,%1,%2,%3};"
        : "+f"(d[0]), "+f"(d[1]), "+f"(d[2]), "+f"(d[3])
        : "r"(a[0]), "r"(a[1]), "r"(a[2]), "r"(a[3]), "r"(b[0]), "r"(b[1]));
}

__device__ __forceinline__ void cpa16(unsigned sm, const void* g) {
    asm volatile("cp.async.cg.shared.global [%0], [%1], 16;" :: "r"(sm), "l"(g));
}

__device__ __forceinline__ void cpa_commit() {
    asm volatile("cp.async.commit_group;");
}

template<int W>
__device__ __forceinline__ void cpa_wait() {
    asm volatile("cp.async.wait_group %0;" :: "n"(W));
}

// ---------------- convert bodies ----------------
template<bool WLO>
__device__ void split_dir_body(const float* in, __half* hi, __half* lo, int n4)
{
    int i = blockIdx.x * blockDim.x + threadIdx.x;
    if (i >= n4) return;
    float4 v = ((const float4*)in)[i];
    __half h0, h1, h2, h3, l0, l1, l2, l3;
    split2(v.x, h0, l0);
    split2(v.y, h1, l1);
    split2(v.z, h2, l2);
    split2(v.w, h3, l3);
    ((__half2*)hi)[2*i+0] = __halves2half2(h0, h1);
    ((__half2*)hi)[2*i+1] = __halves2half2(h2, h3);
    if (WLO) {
        ((__half2*)lo)[2*i+0] = __halves2half2(l0, l1);
        ((__half2*)lo)[2*i+1] = __halves2half2(l2, l3);
    }
}

template<bool SIG, bool WLO>
__device__ void split_trans_body(const float* in, const float* mask,
                                 __half* hi, __half* lo, int P_, int Q_)
{
    __shared__ float t[32][33];
    int p0 = blockIdx.x * 32;
    int q0 = blockIdx.y * 32;
    int tx = threadIdx.x;
    int ty = threadIdx.y;
    #pragma unroll
    for (int dy = 0; dy < 32; dy += 8) {
        size_t idx = (size_t)(p0 + ty + dy) * Q_ + q0 + tx;
        float v = in[idx];
        if (SIG) v *= 1.f / (1.f + __expf(-mask[idx]));
        t[ty + dy][tx] = v;
    }
    __syncthreads();
    #pragma unroll
    for (int dy = 0; dy < 32; dy += 8) {
        float v = t[tx][ty + dy];
        __half h, l;
        split2(v, h, l);
        size_t o = (size_t)(q0 + ty + dy) * P_ + p0 + tx;
        hi[o] = h;
        if (WLO) lo[o] = l;
    }
}

// ---------------- templated-stage 2-pass split-fp16 mma.sync GEMM ----------------
// C = A_hi * (B_hi + B_lo), fp32 accumulate. A-lo never loaded.
// Stage layout: [A_hi (BM*40)][B_hi (BN*40)][B_lo (BN*40)], 4 stages.

template<int BM, int BN, int K, int ST>
__device__ __forceinline__ void g_load(unsigned ub,
    const __half* Ahi, const __half* Bhi, const __half* Blo,
    int m0b, int n0b, int k0, int lr0, int lc)
{
    constexpr int STRIDE = (BM + 2*BN) * 40;
    constexpr unsigned SOFF = (unsigned)(ST * STRIDE * 2);
    #pragma unroll
    for (int h = 0; h < BM / 64; ++h) {
        int r = lr0 + h * 64;
        size_t ga = (size_t)(m0b + r) * K + k0 + lc;
        cpa16(ub + SOFF + (unsigned)((r * 40 + lc) * 2), Ahi + ga);
    }
    #pragma unroll
    for (int h = 0; h < BN / 64; ++h) {
        int r = lr0 + h * 64;
        size_t gb = (size_t)(n0b + r) * K + k0 + lc;
        cpa16(ub + SOFF + (unsigned)((BM*40 + r * 40 + lc) * 2), Bhi + gb);
        cpa16(ub + SOFF + (unsigned)((BM*40 + BN*40 + r * 40 + lc) * 2), Blo + gb);
    }
    cpa_commit();
}

template<int MI, int NJ, int ST>
__device__ __forceinline__ void g_comp(unsigned ub, float (&acc)[MI][NJ][4],
    int wm0, int wn0, int a_row, int a_col, int b_row, int b_col)
{
    constexpr int BM = 2 * MI * 16;
    constexpr int BN = 4 * NJ * 8;
    constexpr int STRIDE = (BM + 2*BN) * 40;
    constexpr unsigned SOFF = (unsigned)(ST * STRIDE * 2);
    constexpr unsigned BH_OFF = (unsigned)(BM * 40 * 2);
    constexpr unsigned BL_OFF = (unsigned)((BM + BN) * 40 * 2);

    #pragma unroll
    for (int ks = 0; ks < 32; ks += 16) {
        uint32_t ah[MI][4];
        uint32_t bh[NJ][2];
        uint32_t bl[NJ][2];
        #pragma unroll
        for (int mi = 0; mi < MI; ++mi) {
            unsigned ao = (unsigned)(((wm0 + mi*16 + a_row) * 40 + ks + a_col) * 2);
            ldm_x4(ah[mi], ub + SOFF + ao);
        }
        #pragma unroll
        for (int njp = 0; njp < NJ / 2; ++njp) {
            unsigned bo = (unsigned)(((wn0 + njp*16 + b_row) * 40 + ks + b_col) * 2);
            uint32_t t[4];
            ldm_x4(t, ub + SOFF + BH_OFF + bo);
            bh[njp*2][0] = t[0];
            bh[njp*2][1] = t[1];
            bh[njp*2+1][0] = t[2];
            bh[njp*2+1][1] = t[3];
            ldm_x4(t, ub + SOFF + BL_OFF + bo);
            bl[njp*2][0] = t[0];
            bl[njp*2][1] = t[1];
            bl[njp*2+1][0] = t[2];
            bl[njp*2+1][1] = t[3];
        }
        #pragma unroll
        for (int mi = 0; mi < MI; ++mi)
            #pragma unroll
            for (int nj = 0; nj < NJ; ++nj)
                mma16816(acc[mi][nj], ah[mi], bh[nj]);
        #pragma unroll
        for (int mi = 0; mi < MI; ++mi)
            #pragma unroll
            for (int nj = 0; nj < NJ; ++nj)
                mma16816(acc[mi][nj], ah[mi], bl[nj]);
    }
}

template<int NK>
__device__ __forceinline__ void g_wait(int c)
{
    if (NK - c >= 3) cpa_wait<2>();
    else if (NK - c == 2) cpa_wait<1>();
    else cpa_wait<0>();
}

// EPI 0: fp32 C (+bias). EPI 1: fp16 hi+lo outputs. EPI 2: mel transposed. EPI 3: fp16 hi-only.
template<int MI, int NJ, int EPI, int N, int K>
__device__ void gemm_body(const __half* Ahi,
                          const __half* Bhi, const __half* Blo,
                          const float* bias, float* C,
                          __half* Oh, __half* Ol)
{
    constexpr int BM = 2 * MI * 16;
    constexpr int BN = 4 * NJ * 8;
    constexpr int NK = K / 32;
    static_assert(NK % 4 == 0, "NK must be divisible by 4");
    extern __shared__ __half dyn[];

    const int tid = threadIdx.x;
    const int warp = tid >> 5;
    const int lane = tid & 31;
    const int wm = warp & 1;
    const int wn = warp >> 1;
    const int m0b = blockIdx.y * BM;
    const int n0b = blockIdx.x * BN;
    const int wm0 = wm * MI * 16;
    const int wn0 = wn * NJ * 8;
    const unsigned ub = smaddr(dyn);

    float acc[MI][NJ][4];
    #pragma unroll
    for (int i = 0; i < MI; ++i)
        #pragma unroll
        for (int j = 0; j < NJ; ++j)
            #pragma unroll
            for (int c = 0; c < 4; ++c) acc[i][j][c] = 0.f;

    const int lr0 = tid >> 2;
    const int lc  = (tid & 3) * 8;
    const int a_row = lane & 15;
    const int a_col = (lane >> 4) * 8;
    const int b_row = (lane & 7) + ((lane >> 4) << 3);
    const int b_col = ((lane >> 3) & 1) * 8;

    g_load<BM,BN,K,0>(ub, Ahi, Bhi, Blo, m0b, n0b, 0,  lr0, lc);
    g_load<BM,BN,K,1>(ub, Ahi, Bhi, Blo, m0b, n0b, 32, lr0, lc);
    g_load<BM,BN,K,2>(ub, Ahi, Bhi, Blo, m0b, n0b, 64, lr0, lc);

    for (int c = 0; c < NK; c += 4) {
        g_wait<NK>(c);
        __syncthreads();
        if (c + 3 < NK) g_load<BM,BN,K,3>(ub, Ahi, Bhi, Blo, m0b, n0b, (c+3)*32, lr0, lc);
        g_comp<MI,NJ,0>(ub, acc, wm0, wn0, a_row, a_col, b_row, b_col);

        g_wait<NK>(c + 1);
        __syncthreads();
        if (c + 4 < NK) g_load<BM,BN,K,0>(ub, Ahi, Bhi, Blo, m0b, n0b, (c+4)*32, lr0, lc);
        g_comp<MI,NJ,1>(ub, acc, wm0, wn0, a_row, a_col, b_row, b_col);

        g_wait<NK>(c + 2);
        __syncthreads();
        if (c + 5 < NK) g_load<BM,BN,K,1>(ub, Ahi, Bhi, Blo, m0b, n0b, (c+5)*32, lr0, lc);
        g_comp<MI,NJ,2>(ub, acc, wm0, wn0, a_row, a_col, b_row, b_col);

        g_wait<NK>(c + 3);
        __syncthreads();
        if (c + 6 < NK) g_load<BM,BN,K,2>(ub, Ahi, Bhi, Blo, m0b, n0b, (c+6)*32, lr0, lc);
        g_comp<MI,NJ,3>(ub, acc, wm0, wn0, a_row, a_col, b_row, b_col);
    }

    const int g = lane >> 2;
    const int tg = lane & 3;
    #pragma unroll
    for (int mi = 0; mi < MI; ++mi)
        #pragma unroll
        for (int nj = 0; nj < NJ; ++nj) {
            int m = m0b + wm0 + mi * 16 + g;
            int n = n0b + wn0 + nj * 8 + tg * 2;
            float v0 = acc[mi][nj][0];
            float v1 = acc[mi][nj][1];
            float v2 = acc[mi][nj][2];
            float v3 = acc[mi][nj][3];
            if (EPI == 0) {
                if (bias) {
                    v0 += bias[n];
                    v1 += bias[n+1];
                    v2 += bias[n];
                    v3 += bias[n+1];
                }
                C[(size_t)m * N + n]       = v0;
                C[(size_t)m * N + n + 1]   = v1;
                C[(size_t)(m+8) * N + n]   = v2;
                C[(size_t)(m+8) * N + n+1] = v3;
            } else if (EPI == 1) {
                __half h0, h1, h2, h3, l0, l1, l2, l3;
                split2(v0, h0, l0);
                split2(v1, h1, l1);
                split2(v2, h2, l2);
                split2(v3, h3, l3);
                *(__half2*)(Oh + (size_t)m * N + n)       = __halves2half2(h0, h1);
                *(__half2*)(Ol + (size_t)m * N + n)       = __halves2half2(l0, l1);
                *(__half2*)(Oh + (size_t)(m+8) * N + n)   = __halves2half2(h2, h3);
                *(__half2*)(Ol + (size_t)(m+8) * N + n)   = __halves2half2(l2, l3);
            } else if (EPI == 3) {
                *(__half2*)(Oh + (size_t)m * N + n) =
                    __halves2half2(__float2half_rn(v0), __float2half_rn(v1));
                *(__half2*)(Oh + (size_t)(m+8) * N + n) =
                    __halves2half2(__float2half_rn(v2), __float2half_rn(v3));
            } else {
                float bn0 = (n < NMEL) ? bias[n] : 0.f;
                float bn1 = (n + 1 < NMEL) ? bias[n + 1] : 0.f;
                v0 += bn0;
                v1 += bn1;
                v2 += bn0;
                v3 += bn1;
                int bb = m >> 10;
                int t = m & 1023;
                int bb2 = (m + 8) >> 10;
                int t2 = (m + 8) & 1023;
                if (n < NMEL) {
                    C[(size_t)(bb*NMEL + n) * NT_SEQ + t] = v0;
                    C[(size_t)(bb2*NMEL + n) * NT_SEQ + t2] = v2;
                }
                if (n + 1 < NMEL) {
                    C[(size_t)(bb*NMEL + n+1) * NT_SEQ + t] = v1;
                    C[(size_t)(bb2*NMEL + n+1) * NT_SEQ + t2] = v3;
                }
            }
        }
}

// ---------------- conv / ln bodies ----------------
template<bool DO_GELU>
__device__ void conv_body(const float* in, const float* w, const float* bias, float* out)
{
    __shared__ float sm[10][DD];
    const int blk = blockIdx.x;
    const int b  = blk / (NT_SEQ / 8);
    const int t0 = (blk % (NT_SEQ / 8)) * 8;
    const float* inb = in + (size_t)b * NT_SEQ * DD;
    const int tid = threadIdx.x;

    for (int idx = tid; idx < 10 * DD; idx += 256) {
        int r = idx / DD;
        int c = idx % DD;
        int t = t0 - 1 + r;
        sm[r][c] = (t >= 0 && t < NT_SEQ) ? inb[(size_t)t*DD + c] : 0.f;
    }
    __syncthreads();

    const int cbase = tid * 4;
    const int g = cbase >> 6;
    float acc[4][8];
    #pragma unroll
    for (int cc = 0; cc < 4; ++cc) {
        float bb = bias[cbase + cc];
        #pragma unroll
        for (int tt = 0; tt < 8; ++tt) acc[cc][tt] = bb;
    }
    const float* wp = w + (size_t)cbase * 192;

    for (int ci = 0; ci < 64; ++ci) {
        float x[10];
        #pragma unroll
        for (int r = 0; r < 10; ++r) x[r] = sm[r][g*64 + ci];
        #pragma unroll
        for (int cc = 0; cc < 4; ++cc) {
            float w0 = wp[cc*192 + ci*3 + 0];
            float w1 = wp[cc*192 + ci*3 + 1];
            float w2 = wp[cc*192 + ci*3 + 2];
            #pragma unroll
            for (int tt = 0; tt < 8; ++tt)
                acc[cc][tt] += w0*x[tt] + w1*x[tt+1] + w2*x[tt+2];
        }
    }

    float* outb = out + (size_t)b * NT_SEQ * DD;
    #pragma unroll
    for (int tt = 0; tt < 8; ++tt) {
        float v0 = acc[0][tt];
        float v1 = acc[1][tt];
        float v2 = acc[2][tt];
        float v3 = acc[3][tt];
        if (DO_GELU) {
            v0 = 0.5f*v0*(1.f + erff(v0*0.70710678118654752f));
            v1 = 0.5f*v1*(1.f + erff(v1*0.70710678118654752f));
            v2 = 0.5f*v2*(1.f + erff(v2*0.70710678118654752f));
            v3 = 0.5f*v3*(1.f + erff(v3*0.70710678118654752f));
        }
        float4 o;
        o.x = v0;
        o.y = v1;
        o.z = v2;
        o.w = v3;
        *(float4*)(outb + (size_t)(t0+tt)*DD + cbase) = o;
    }
}

__device__ void ln_body(const float* in, const float* gam, const float* bet, __half* oh)
{
    __shared__ float s1[8];
    __shared__ float s2[8];
    const int row = blockIdx.x;
    const int tid = threadIdx.x;
    const float4* x4 = (const float4*)(in + (size_t)row * DD);
    float4 v = x4[tid];
    float s = v.x + v.y + v.z + v.w;
    float q = v.x*v.x + v.y*v.y + v.z*v.z + v.w*v.w;
    #pragma unroll
    for (int o = 16; o > 0; o >>= 1) {
        s += __shfl_xor_sync(0xFFFFFFFFu, s, o);
        q += __shfl_xor_sync(0xFFFFFFFFu, q, o);
    }
    if ((tid & 31) == 0) {
        s1[tid >> 5] = s;
        s2[tid >> 5] = q;
    }
    __syncthreads();
    float ts = 0.f;
    float tq = 0.f;
    #pragma unroll
    for (int i = 0; i < 8; ++i) {
        ts += s1[i];
        tq += s2[i];
    }
    const float mu   = ts * (1.f / DD);
    const float var  = tq * (1.f / DD) - mu * mu;
    const float rstd = rsqrtf(var + 1e-5f);
    float4 g4 = ((const float4*)gam)[tid];
    float4 b4 = ((const float4*)bet)[tid];
    float y0 = (v.x - mu) * rstd * g4.x + b4.x;
    float y1 = (v.y - mu) * rstd * g4.y + b4.y;
    float y2 = (v.z - mu) * rstd * g4.z + b4.z;
    float y3 = (v.w - mu) * rstd * g4.w + b4.w;
    size_t o = (size_t)row * DD + tid * 4;
    ((__half2*)(oh + o))[0] = __halves2half2(__float2half_rn(y0), __float2half_rn(y1));
    ((__half2*)(oh + o))[1] = __halves2half2(__float2half_rn(y2), __float2half_rn(y3));
}

// ---------------- wrapper kernels ----------------
__global__ void k_split_Win(const float* W_in) { split_dir_body<false>(W_in, g_WinD_h, 0, DD*LL/4); }
__global__ void k_split_Wd(const float* Wd)    { split_dir_body<true>(Wd, g_WdD_h, g_WdD_l, DD*LL/4); }
__global__ void k_split_llama(const float* x)  { split_dir_body<false>(x, g_Lla_h, 0, ROWS*LL/4); }
__global__ void k_split_Pdir(const float* P)   { split_dir_body<true>(P, g_Pd_h, g_Pd_l, DD*DD/4); }

__global__ void k_trans_WinT(const float* W_in) { split_trans_body<false,true>(W_in, 0, g_WinT_h, g_WinT_l, DD, LL); }
__global__ void k_trans_PT(const float* P)      { split_trans_body<false,true>(P, 0, g_Pt_h, g_Pt_l, DD, DD); }
__global__ void k_trans_wpT()                   { split_trans_body<false,true>(g_wproj, 0, g_wpT_h, g_wpT_l, DD, DD); }
__global__ void k_trans_S(const float* mask)    { split_trans_body<true,false>(g_wprime, mask, g_S_h, 0, DD, DD); }
__global__ void k_trans_uT()                    { split_trans_body<false,true>(g_u, 0, g_uT_h, g_uT_l, DD, DD); }
__global__ void k_trans_QT()                    { split_trans_body<false,false>(g_Qf, 0, g_QT_h, 0, DD, DD); }

__global__ void k_split_mel(const float* Wmel)
{
    int i = blockIdx.x * 256 + threadIdx.x;
    int r = i >> 10;
    float v = (r < NMEL) ? Wmel[(size_t)r * DD + (i & 1023)] : 0.f;
    __half h, l;
    split2(v, h, l);
    g_Wmel_h[i] = h;
    g_Wmel_l[i] = l;
}

__global__ __launch_bounds__(256) void k_gemm_wproj(const float* bd)
{ gemm_body<2,4,0,DD,LL>(g_WinD_h, g_WdD_h, g_WdD_l, bd, g_wproj, 0, 0); }

__global__ __launch_bounds__(256) void k_gemm_t1()
{ gemm_body<2,4,3,DD,DD>(g_Pt_h, g_wpT_h, g_wpT_l, 0, 0, g_t1s_h, 0); }

__global__ __launch_bounds__(256) void k_gemm_wprime()
{ gemm_body<2,4,0,DD,DD>(g_t1s_h, g_Pt_h, g_Pt_l, 0, g_wprime, 0, 0); }

__global__ __launch_bounds__(256) void k_gemm_u()
{ gemm_body<2,4,0,DD,DD>(g_S_h, g_Pd_h, g_Pd_l, 0, g_u, 0, 0); }

__global__ __launch_bounds__(256) void k_gemm_Q()
{ gemm_body<2,4,0,DD,DD>(g_Pd_h, g_uT_h, g_uT_l, 0, g_Qf, 0, 0); }

__global__ __launch_bounds__(256) void k_gemm_WcT()
{ gemm_body<2,4,1,LL,DD>(g_QT_h, g_WinT_h, g_WinT_l, 0, 0, g_WcTs_h, g_WcTs_l); }

__global__ __launch_bounds__(256) void k_gemm_fused()
{ gemm_body<2,4,0,DD,LL>(g_Lla_h, g_WcTs_h, g_WcTs_l, g_bvec, g_fused, 0, 0); }

__global__ __launch_bounds__(256) void k_gemm_mel(const float* bmel, float* out)
{ gemm_body<2,2,2,128,DD>(g_xn_h, g_Wmel_h, g_Wmel_l, bmel, out, 0, 0); }

// bvec[e] = sum_d b_in[d] * Q[d,e] — 16 blocks, 4 partials per e, smem reduce.
__global__ __launch_bounds__(256) void k_bvec(const float* b_in)
{
    __shared__ float red[4][64];
    int e = blockIdx.x * 64 + (threadIdx.x & 63);
    int part = threadIdx.x >> 6;
    float s = 0.f;
    for (int d = part * 256; d < part * 256 + 256; ++d)
        s += b_in[d] * g_Qf[(size_t)d * DD + e];
    red[part][threadIdx.x & 63] = s;
    __syncthreads();
    if (part == 0)
        g_bvec[e] = red[0][threadIdx.x] + red[1][threadIdx.x]
                  + red[2][threadIdx.x] + red[3][threadIdx.x];
}

__global__ __launch_bounds__(256) void k_conv1(const float* w, const float* b)
{ conv_body<true>(g_fused, w, b, g_h1); }

__global__ __launch_bounds__(256) void k_conv2(const float* w, const float* b)
{ conv_body<false>(g_h1, w, b, g_h2); }

__global__ __launch_bounds__(256) void k_ln(const float* g, const float* b)
{ ln_body(g_h2, g, b, g_xn_h); }

// ---------------- launch ----------------
extern "C" void kernel_launch(void* const* d_in, const int* in_sizes, int n_in,
                              void* d_out, int out_size)
{
    (void)in_sizes;
    (void)n_in;
    (void)out_size;
    const float* llama = (const float*)d_in[0];
    const float* W_in  = (const float*)d_in[2];
    const float* b_in  = (const float*)d_in[3];
    const float* P     = (const float*)d_in[4];
    const float* smask = (const float*)d_in[5];
    const float* Wd    = (const float*)d_in[6];
    const float* bd    = (const float*)d_in[7];
    const float* c1w   = (const float*)d_in[8];
    const float* c1b   = (const float*)d_in[9];
    const float* c2w   = (const float*)d_in[10];
    const float* c2b   = (const float*)d_in[11];
    const float* lng   = (const float*)d_in[12];
    const float* lnb   = (const float*)d_in[13];
    const float* Wmel  = (const float*)d_in[14];
    const float* bmel  = (const float*)d_in[15];
    float* out = (float*)d_out;

    // 4 stages * (BM + 2*BN) * 40 elems * 2B
    const int smem_64_128 = 4 * (64 + 256) * 40 * 2;   // 102400 -> 2 CTAs/SM
    const int smem_64_64  = 4 * (64 + 128) * 40 * 2;   // 61440

    cudaFuncSetAttribute(k_gemm_wproj,  cudaFuncAttributeMaxDynamicSharedMemorySize, smem_64_128);
    cudaFuncSetAttribute(k_gemm_t1,     cudaFuncAttributeMaxDynamicSharedMemorySize, smem_64_128);
    cudaFuncSetAttribute(k_gemm_wprime, cudaFuncAttributeMaxDynamicSharedMemorySize, smem_64_128);
    cudaFuncSetAttribute(k_gemm_u,      cudaFuncAttributeMaxDynamicSharedMemorySize, smem_64_128);
    cudaFuncSetAttribute(k_gemm_Q,      cudaFuncAttributeMaxDynamicSharedMemorySize, smem_64_128);
    cudaFuncSetAttribute(k_gemm_WcT,    cudaFuncAttributeMaxDynamicSharedMemorySize, smem_64_128);
    cudaFuncSetAttribute(k_gemm_fused,  cudaFuncAttributeMaxDynamicSharedMemorySize, smem_64_128);
    cudaFuncSetAttribute(k_gemm_mel,    cudaFuncAttributeMaxDynamicSharedMemorySize, smem_64_64);

    dim3 tb(32, 8);

    // FROZEN launch order (round-12; known-good with the bench container).
    k_split_Win<<<DD*LL/4/256, 256>>>(W_in);
    k_split_Wd<<<DD*LL/4/256, 256>>>(Wd);
    k_trans_WinT<<<dim3(DD/32, LL/32), tb>>>(W_in);
    k_split_llama<<<ROWS*LL/4/256, 256>>>(llama);
    k_split_Pdir<<<DD*DD/4/256, 256>>>(P);
    k_trans_PT<<<dim3(DD/32, DD/32), tb>>>(P);
    k_split_mel<<<128*DD/256, 256>>>(Wmel);

    k_gemm_wproj<<<dim3(DD/128, DD/64), 256, smem_64_128>>>(bd);
    k_trans_wpT<<<dim3(DD/32, DD/32), tb>>>();
    k_gemm_t1<<<dim3(DD/128, DD/64), 256, smem_64_128>>>();
    k_gemm_wprime<<<dim3(DD/128, DD/64), 256, smem_64_128>>>();
    k_trans_S<<<dim3(DD/32, DD/32), tb>>>(smask);
    k_gemm_u<<<dim3(DD/128, DD/64), 256, smem_64_128>>>();
    k_trans_uT<<<dim3(DD/32, DD/32), tb>>>();
    k_gemm_Q<<<dim3(DD/128, DD/64), 256, smem_64_128>>>();
    k_trans_QT<<<dim3(DD/32, DD/32), tb>>>();
    k_bvec<<<DD/64, 256>>>(b_in);
    k_gemm_WcT<<<dim3(LL/128, DD/64), 256, smem_64_128>>>();
    k_gemm_fused<<<dim3(DD/128, ROWS/64), 256, smem_64_128>>>();

    k_conv1<<<NB * (NT_SEQ/8), 256>>>(c1w, c1b);
    k_conv2<<<NB * (NT_SEQ/8), 256>>>(c2w, c2b);
    k_ln<<<ROWS, 256>>>(lng, lnb);
    k_gemm_mel<<<dim3(2, ROWS/64), 256, smem_64_64>>>(bmel, out);
}